// round 4
// baseline (speedup 1.0000x reference)
#include <cuda_runtime.h>
#include <math.h>

#define N_   50000
#define E_   800000
#define HALF_E (E_ / 2)
#define H_   64
#define FE_  32
#define NT_  3
#define ET_  4
#define NEG_ 0.2f

// ---------------- device scratch ----------------
__device__ __align__(16) float g_e0[E_ * H_];   // ea buffer layer1 -> layer2
__device__ __align__(16) float g_e1[E_ * H_];   // ea buffer layer2 -> layer3
__device__ __align__(16) float g_h [N_ * H_];
__device__ __align__(16) float g_s1[N_ * H_];   // sum ex * ea
__device__ __align__(16) float g_s2[N_ * H_];   // sum ex * h[src]
__device__ __align__(16) float g_out[N_ * H_];  // conv output
__device__ float g_sI[N_];
__device__ float g_sJ[N_];
__device__ float g_sum[N_];

// ---------------- helpers ----------------
__device__ __forceinline__ float lrelu(float x) { return x > 0.f ? x : NEG_ * x; }

// ---------------- init: zero accumulators ----------------
__global__ void init_kernel() {
    int i = blockIdx.x * blockDim.x + threadIdx.x;
    if (i < N_ * H_) { g_s1[i] = 0.f; g_s2[i] = 0.f; }
    if (i < N_) g_sum[i] = 0.f;
}

// ---------------- node pass: h = act(x)@Whl[t]+bhl[t]; sI=h@Wi; sJ=h@Wj ----
template <bool RELU>
__global__ void __launch_bounds__(128)
node_kernel(const float* __restrict__ xin, const int* __restrict__ ntype,
            const float* __restrict__ Whl, const float* __restrict__ bhl,
            const float* __restrict__ Watt) {
    __shared__ float4 sW[NT_ * H_ * 16];  // 48KB: all 3 type weight matrices
    for (int i = threadIdx.x; i < NT_ * H_ * 16; i += blockDim.x)
        sW[i] = reinterpret_cast<const float4*>(Whl)[i];
    __syncthreads();

    int n = blockIdx.x * blockDim.x + threadIdx.x;
    if (n >= N_) return;
    int t = ntype[n];

    const float4* b4 = reinterpret_cast<const float4*>(bhl) + t * 16;
    float4 acc[16];
#pragma unroll
    for (int o4 = 0; o4 < 16; o4++) acc[o4] = __ldg(b4 + o4);

    const float4* x4 = reinterpret_cast<const float4*>(xin) + n * 16;
    const float4* W4 = sW + t * 1024;
#pragma unroll 1
    for (int kc = 0; kc < 16; kc++) {
        float4 v4 = x4[kc];
        if (RELU) {
            v4.x = fmaxf(v4.x, 0.f); v4.y = fmaxf(v4.y, 0.f);
            v4.z = fmaxf(v4.z, 0.f); v4.w = fmaxf(v4.w, 0.f);
        }
        float vv[4] = {v4.x, v4.y, v4.z, v4.w};
#pragma unroll
        for (int j = 0; j < 4; j++) {
            float v = vv[j];
            const float4* wr = W4 + (kc * 4 + j) * 16;
#pragma unroll
            for (int o4 = 0; o4 < 16; o4++) {
                float4 w = wr[o4];
                acc[o4].x += v * w.x; acc[o4].y += v * w.y;
                acc[o4].z += v * w.z; acc[o4].w += v * w.w;
            }
        }
    }

    float sI = 0.f, sJ = 0.f;
#pragma unroll
    for (int o4 = 0; o4 < 16; o4++) {
        float4 a = acc[o4];
        sI += a.x * __ldg(Watt + o4 * 4)     + a.y * __ldg(Watt + o4 * 4 + 1)
            + a.z * __ldg(Watt + o4 * 4 + 2) + a.w * __ldg(Watt + o4 * 4 + 3);
        sJ += a.x * __ldg(Watt + 64 + o4 * 4)     + a.y * __ldg(Watt + 64 + o4 * 4 + 1)
            + a.z * __ldg(Watt + 64 + o4 * 4 + 2) + a.w * __ldg(Watt + 64 + o4 * 4 + 3);
    }

    float4* h4 = reinterpret_cast<float4*>(g_h) + n * 16;
#pragma unroll
    for (int o4 = 0; o4 < 16; o4++) h4[o4] = acc[o4];
    g_sI[n] = sI;
    g_sJ[n] = sJ;
}

// ---------------- fused edge pass epilogue ----------------
template <bool EHEAD, bool WRITE_EA>
__device__ __forceinline__ void edge_epilogue(
    float4 (&acc)[16], int e,
    const int* __restrict__ ei, const int* __restrict__ etype,
    const float* sWe, const float* sEteW,
    float* __restrict__ eaout,
    const float* sWec, const float* sBec, float* __restrict__ eout)
{
    int t = etype[e];
    int src = ei[e];
    int dst = ei[E_ + e];

    float pre = 0.f, eo = 0.f;
    const float* wec = sWec + t * 64;
#pragma unroll
    for (int o4 = 0; o4 < 16; o4++) {
        float4 a = acc[o4];
        a.x = lrelu(a.x); a.y = lrelu(a.y); a.z = lrelu(a.z); a.w = lrelu(a.w);
        acc[o4] = a;   // keep ea in regs
        pre += a.x * sWe[o4 * 4]     + a.y * sWe[o4 * 4 + 1]
             + a.z * sWe[o4 * 4 + 2] + a.w * sWe[o4 * 4 + 3];
        if (EHEAD) {
            eo += fmaxf(a.x, 0.f) * wec[o4 * 4]     + fmaxf(a.y, 0.f) * wec[o4 * 4 + 1]
                + fmaxf(a.z, 0.f) * wec[o4 * 4 + 2] + fmaxf(a.w, 0.f) * wec[o4 * 4 + 3];
        }
    }
    if (EHEAD) eout[e] = eo + sBec[t];

    float lg = lrelu(g_sI[dst] + g_sJ[src] + pre + sEteW[t]);
    float ex = expf(lg);

    atomicAdd(&g_sum[dst], ex);

    const float4* h4 = reinterpret_cast<const float4*>(g_h) + src * 16;
    float4* s14 = reinterpret_cast<float4*>(g_s1) + dst * 16;
    float4* s24 = reinterpret_cast<float4*>(g_s2) + dst * 16;
    float4* out4 = WRITE_EA ? (reinterpret_cast<float4*>(eaout) + (long)e * 16) : nullptr;

#pragma unroll
    for (int o4 = 0; o4 < 16; o4++) {
        float4 a = acc[o4];
        if (WRITE_EA) out4[o4] = a;
        float4 v;
        v.x = a.x * ex; v.y = a.y * ex; v.z = a.z * ex; v.w = a.w * ex;
        atomicAdd(s14 + o4, v);
        float4 hh = h4[o4];
        hh.x *= ex; hh.y *= ex; hh.z *= ex; hh.w *= ex;
        atomicAdd(s24 + o4, hh);
    }
}

// ---------------- fused edge pass: GEMM + logit + exp + scatter ------------
template <int IN, bool RELU, bool EHEAD, bool WRITE_EA>
__global__ void __launch_bounds__(128)
edge_fused_kernel(const float* __restrict__ ein, const int* __restrict__ ei,
                  const int* __restrict__ etype, const float* __restrict__ Wea,
                  const float* __restrict__ Watt, const float* __restrict__ Ete,
                  float* __restrict__ eaout,
                  const float* __restrict__ Wec, const float* __restrict__ bec,
                  float* __restrict__ eout) {
    __shared__ float4 sW[IN * 16];
    __shared__ float  sWe[64];
    __shared__ float  sEteW[ET_];
    __shared__ float  sWec[ET_ * 64];
    __shared__ float  sBec[ET_];
    for (int i = threadIdx.x; i < IN * 16; i += blockDim.x)
        sW[i] = reinterpret_cast<const float4*>(Wea)[i];
    if (threadIdx.x < 64) sWe[threadIdx.x] = Watt[132 + threadIdx.x];
    if (threadIdx.x < ET_) {
        float a = 0.f;
#pragma unroll
        for (int j = 0; j < 4; j++) a += lrelu(Ete[threadIdx.x * 4 + j]) * Watt[128 + j];
        sEteW[threadIdx.x] = a;
    }
    if (EHEAD) {
        for (int i = threadIdx.x; i < ET_ * 64; i += blockDim.x) sWec[i] = Wec[i];
        if (threadIdx.x < ET_) sBec[threadIdx.x] = bec[threadIdx.x];
    }
    __syncthreads();

    int e0 = blockIdx.x * blockDim.x + threadIdx.x;   // < HALF_E by grid sizing
    int e1 = e0 + HALF_E;

    float4 acc0[16], acc1[16];
#pragma unroll
    for (int o4 = 0; o4 < 16; o4++) {
        acc0[o4] = make_float4(0.f, 0.f, 0.f, 0.f);
        acc1[o4] = make_float4(0.f, 0.f, 0.f, 0.f);
    }

    const float4* in4 = reinterpret_cast<const float4*>(ein);
    const float4* r0 = in4 + (long)e0 * (IN / 4);
    const float4* r1 = in4 + (long)e1 * (IN / 4);
#pragma unroll 1
    for (int kc = 0; kc < IN / 4; kc++) {
        float4 v0 = r0[kc];
        float4 v1 = r1[kc];
        if (RELU) {
            v0.x = fmaxf(v0.x, 0.f); v0.y = fmaxf(v0.y, 0.f);
            v0.z = fmaxf(v0.z, 0.f); v0.w = fmaxf(v0.w, 0.f);
            v1.x = fmaxf(v1.x, 0.f); v1.y = fmaxf(v1.y, 0.f);
            v1.z = fmaxf(v1.z, 0.f); v1.w = fmaxf(v1.w, 0.f);
        }
        float a0[4] = {v0.x, v0.y, v0.z, v0.w};
        float a1[4] = {v1.x, v1.y, v1.z, v1.w};
#pragma unroll
        for (int j = 0; j < 4; j++) {
            float u0 = a0[j], u1 = a1[j];
            const float4* wr = sW + (kc * 4 + j) * 16;
#pragma unroll
            for (int o4 = 0; o4 < 16; o4++) {
                float4 w = wr[o4];
                acc0[o4].x += u0 * w.x; acc0[o4].y += u0 * w.y;
                acc0[o4].z += u0 * w.z; acc0[o4].w += u0 * w.w;
                acc1[o4].x += u1 * w.x; acc1[o4].y += u1 * w.y;
                acc1[o4].z += u1 * w.z; acc1[o4].w += u1 * w.w;
            }
        }
    }

    edge_epilogue<EHEAD, WRITE_EA>(acc0, e0, ei, etype, sWe, sEteW, eaout, sWec, sBec, eout);
    edge_epilogue<EHEAD, WRITE_EA>(acc1, e1, ei, etype, sWe, sEteW, eaout, sWec, sBec, eout);
}

// ---------------- finish: out = (s2 @ Wlin[:H] + s1 @ Wlin[H:]) / sum -------
__global__ void __launch_bounds__(128)
finish_kernel(const float* __restrict__ Wlin) {
    __shared__ float4 sW[128 * 16];   // 32KB: full (2H x H) Wlin
    for (int i = threadIdx.x; i < 128 * 16; i += blockDim.x)
        sW[i] = reinterpret_cast<const float4*>(Wlin)[i];
    __syncthreads();

    int n = blockIdx.x * blockDim.x + threadIdx.x;
    if (n >= N_) return;

    float4 acc[16];
#pragma unroll
    for (int o4 = 0; o4 < 16; o4++) acc[o4] = make_float4(0.f, 0.f, 0.f, 0.f);

    const float4* r2 = reinterpret_cast<const float4*>(g_s2) + n * 16;  // k 0..63
    const float4* r1 = reinterpret_cast<const float4*>(g_s1) + n * 16;  // k 64..127
#pragma unroll 1
    for (int kc = 0; kc < 16; kc++) {
        float4 v4 = r2[kc];
        float vv[4] = {v4.x, v4.y, v4.z, v4.w};
#pragma unroll
        for (int j = 0; j < 4; j++) {
            float v = vv[j];
            const float4* wr = sW + (kc * 4 + j) * 16;
#pragma unroll
            for (int o4 = 0; o4 < 16; o4++) {
                float4 w = wr[o4];
                acc[o4].x += v * w.x; acc[o4].y += v * w.y;
                acc[o4].z += v * w.z; acc[o4].w += v * w.w;
            }
        }
    }
#pragma unroll 1
    for (int kc = 0; kc < 16; kc++) {
        float4 v4 = r1[kc];
        float vv[4] = {v4.x, v4.y, v4.z, v4.w};
#pragma unroll
        for (int j = 0; j < 4; j++) {
            float v = vv[j];
            const float4* wr = sW + (64 + kc * 4 + j) * 16;
#pragma unroll
            for (int o4 = 0; o4 < 16; o4++) {
                float4 w = wr[o4];
                acc[o4].x += v * w.x; acc[o4].y += v * w.y;
                acc[o4].z += v * w.z; acc[o4].w += v * w.w;
            }
        }
    }

    float inv = 1.f / (g_sum[n] + 1e-16f);
    float4* out4 = reinterpret_cast<float4*>(g_out) + n * 16;
#pragma unroll
    for (int o4 = 0; o4 < 16; o4++) {
        float4 a = acc[o4];
        a.x *= inv; a.y *= inv; a.z *= inv; a.w *= inv;
        out4[o4] = a;
    }
}

// ---------------- final node head ----------------
__global__ void out_node_kernel(const int* __restrict__ ntype,
                                const float* __restrict__ Wnc, const float* __restrict__ bnc,
                                float* __restrict__ dout) {
    int n = blockIdx.x * blockDim.x + threadIdx.x;
    if (n >= N_) return;
    int t = ntype[n];
    const float* hr = g_out + n * 64;
    const float* w = Wnc + t * 64;
    float a = bnc[t];
#pragma unroll
    for (int k = 0; k < 64; k++) a += fmaxf(hr[k], 0.f) * __ldg(w + k);
    dout[n] = a;
}

// ---------------- launcher ----------------
extern "C" void kernel_launch(void* const* d_in, const int* in_sizes, int n_in,
                              void* d_out, int out_size) {
    const float* x     = (const float*)d_in[0];
    const int*   ei    = (const int*)d_in[1];
    const int*   ntype = (const int*)d_in[2];
    const int*   etype = (const int*)d_in[3];
    const float* eattr = (const float*)d_in[4];

    const float* Whl[3]  = {(const float*)d_in[5],  (const float*)d_in[11], (const float*)d_in[17]};
    const float* bhl[3]  = {(const float*)d_in[6],  (const float*)d_in[12], (const float*)d_in[18]};
    const float* Ete[3]  = {(const float*)d_in[7],  (const float*)d_in[13], (const float*)d_in[19]};
    const float* Wea[3]  = {(const float*)d_in[8],  (const float*)d_in[14], (const float*)d_in[20]};
    const float* Watt[3] = {(const float*)d_in[9],  (const float*)d_in[15], (const float*)d_in[21]};
    const float* Wlin[3] = {(const float*)d_in[10], (const float*)d_in[16], (const float*)d_in[22]};
    const float* Wnc = (const float*)d_in[23];
    const float* bnc = (const float*)d_in[24];
    const float* Wec = (const float*)d_in[25];
    const float* bec = (const float*)d_in[26];

    float *e0, *e1, *outBuf;
    cudaGetSymbolAddress((void**)&e0, g_e0);
    cudaGetSymbolAddress((void**)&e1, g_e1);
    cudaGetSymbolAddress((void**)&outBuf, g_out);

    const int nodeBlocks = (N_ + 127) / 128;
    const int eaBlocks   = HALF_E / 128;          // 3125
    const int initBlocks = (N_ * H_ + 255) / 256;

    float* doutN = (float*)d_out;        // node head [0, N)
    float* doutE = (float*)d_out + N_;   // edge head [N, N+E)

    // ---- layer 1 ----
    init_kernel<<<initBlocks, 256>>>();
    node_kernel<false><<<nodeBlocks, 128>>>(x, ntype, Whl[0], bhl[0], Watt[0]);
    edge_fused_kernel<FE_, false, false, true><<<eaBlocks, 128>>>(
        eattr, ei, etype, Wea[0], Watt[0], Ete[0], e0, nullptr, nullptr, nullptr);
    finish_kernel<<<nodeBlocks, 128>>>(Wlin[0]);

    // ---- layer 2 ----
    init_kernel<<<initBlocks, 256>>>();
    node_kernel<true><<<nodeBlocks, 128>>>(outBuf, ntype, Whl[1], bhl[1], Watt[1]);
    edge_fused_kernel<H_, true, false, true><<<eaBlocks, 128>>>(
        e0, ei, etype, Wea[1], Watt[1], Ete[1], e1, nullptr, nullptr, nullptr);
    finish_kernel<<<nodeBlocks, 128>>>(Wlin[1]);

    // ---- layer 3 ----
    init_kernel<<<initBlocks, 256>>>();
    node_kernel<true><<<nodeBlocks, 128>>>(outBuf, ntype, Whl[2], bhl[2], Watt[2]);
    edge_fused_kernel<H_, true, true, false><<<eaBlocks, 128>>>(
        e1, ei, etype, Wea[2], Watt[2], Ete[2], nullptr, Wec, bec, doutE);
    finish_kernel<<<nodeBlocks, 128>>>(Wlin[2]);

    out_node_kernel<<<nodeBlocks, 128>>>(ntype, Wnc, bnc, doutN);
}

// round 5
// speedup vs baseline: 1.1116x; 1.1116x over previous
#include <cuda_runtime.h>
#include <math.h>

#define N_   50000
#define E_   800000
#define HALF_E (E_ / 2)
#define H_   64
#define FE_  32
#define NT_  3
#define ET_  4
#define NEG_ 0.2f

// ---------------- device scratch ----------------
__device__ __align__(16) float g_e0[E_ * H_];   // ea buffer layer1 -> layer2
__device__ __align__(16) float g_e1[E_ * H_];   // ea buffer layer2 -> layer3
__device__ __align__(16) float g_ea3[E_ * H_];  // ea buffer layer3 (for gather)
__device__ __align__(16) float g_h [N_ * H_];
__device__ __align__(16) float g_s1[N_ * H_];   // sum ex * ea
__device__ __align__(16) float g_s2[N_ * H_];   // sum ex * h[src]
__device__ __align__(16) float g_out[N_ * H_];  // conv output
__device__ float g_sI[N_];
__device__ float g_sJ[N_];
__device__ float g_sum[N_];
__device__ float g_logit[E_];
// CSR (built once per launch; graph identical across layers)
__device__ int g_deg[N_];
__device__ int g_off[N_ + 1];
__device__ int g_cur[N_];
__device__ int g_perm[E_];

// ---------------- helpers ----------------
__device__ __forceinline__ float lrelu(float x) { return x > 0.f ? x : NEG_ * x; }

// ================= CSR construction =================
__global__ void zero_deg_kernel() {
    int i = blockIdx.x * blockDim.x + threadIdx.x;
    if (i < N_) g_deg[i] = 0;
}

__global__ void hist_kernel(const int* __restrict__ ei) {
    int e = blockIdx.x * blockDim.x + threadIdx.x;
    if (e < E_) atomicAdd(&g_deg[ei[E_ + e]], 1);
}

// single-block exclusive scan over g_deg (N_=50000)
__global__ void scan_kernel() {
    __shared__ int warpsum[32];
    __shared__ int s_carry;
    int tid = threadIdx.x;
    int lane = tid & 31, wid = tid >> 5;
    if (tid == 0) s_carry = 0;
    __syncthreads();
    for (int base = 0; base < N_; base += 1024) {
        int i = base + tid;
        int v = (i < N_) ? g_deg[i] : 0;
        int incl = v;
#pragma unroll
        for (int d = 1; d < 32; d <<= 1) {
            int t = __shfl_up_sync(0xFFFFFFFFu, incl, d);
            if (lane >= d) incl += t;
        }
        if (lane == 31) warpsum[wid] = incl;
        __syncthreads();
        if (wid == 0) {
            int w = warpsum[lane];
#pragma unroll
            for (int d = 1; d < 32; d <<= 1) {
                int t = __shfl_up_sync(0xFFFFFFFFu, w, d);
                if (lane >= d) w += t;
            }
            warpsum[lane] = w;
        }
        __syncthreads();
        int off = s_carry + (wid > 0 ? warpsum[wid - 1] : 0);
        int excl = off + incl - v;
        if (i < N_) { g_off[i] = excl; g_cur[i] = excl; }
        __syncthreads();
        if (tid == 0) s_carry += warpsum[31];
        __syncthreads();
    }
    if (tid == 0) g_off[N_] = s_carry;
}

__global__ void scatter_perm_kernel(const int* __restrict__ ei) {
    int e = blockIdx.x * blockDim.x + threadIdx.x;
    if (e >= E_) return;
    int pos = atomicAdd(&g_cur[ei[E_ + e]], 1);
    g_perm[pos] = e;
}

// ================= node pass =================
template <bool RELU>
__global__ void __launch_bounds__(128)
node_kernel(const float* __restrict__ xin, const int* __restrict__ ntype,
            const float* __restrict__ Whl, const float* __restrict__ bhl,
            const float* __restrict__ Watt) {
    __shared__ float4 sW[NT_ * H_ * 16];  // 48KB: all 3 type weight matrices
    for (int i = threadIdx.x; i < NT_ * H_ * 16; i += blockDim.x)
        sW[i] = reinterpret_cast<const float4*>(Whl)[i];
    __syncthreads();

    int n = blockIdx.x * blockDim.x + threadIdx.x;
    if (n >= N_) return;
    int t = ntype[n];

    const float4* b4 = reinterpret_cast<const float4*>(bhl) + t * 16;
    float4 acc[16];
#pragma unroll
    for (int o4 = 0; o4 < 16; o4++) acc[o4] = __ldg(b4 + o4);

    const float4* x4 = reinterpret_cast<const float4*>(xin) + n * 16;
    const float4* W4 = sW + t * 1024;
#pragma unroll 1
    for (int kc = 0; kc < 16; kc++) {
        float4 v4 = x4[kc];
        if (RELU) {
            v4.x = fmaxf(v4.x, 0.f); v4.y = fmaxf(v4.y, 0.f);
            v4.z = fmaxf(v4.z, 0.f); v4.w = fmaxf(v4.w, 0.f);
        }
        float vv[4] = {v4.x, v4.y, v4.z, v4.w};
#pragma unroll
        for (int j = 0; j < 4; j++) {
            float v = vv[j];
            const float4* wr = W4 + (kc * 4 + j) * 16;
#pragma unroll
            for (int o4 = 0; o4 < 16; o4++) {
                float4 w = wr[o4];
                acc[o4].x += v * w.x; acc[o4].y += v * w.y;
                acc[o4].z += v * w.z; acc[o4].w += v * w.w;
            }
        }
    }

    float sI = 0.f, sJ = 0.f;
#pragma unroll
    for (int o4 = 0; o4 < 16; o4++) {
        float4 a = acc[o4];
        sI += a.x * __ldg(Watt + o4 * 4)     + a.y * __ldg(Watt + o4 * 4 + 1)
            + a.z * __ldg(Watt + o4 * 4 + 2) + a.w * __ldg(Watt + o4 * 4 + 3);
        sJ += a.x * __ldg(Watt + 64 + o4 * 4)     + a.y * __ldg(Watt + 64 + o4 * 4 + 1)
            + a.z * __ldg(Watt + 64 + o4 * 4 + 2) + a.w * __ldg(Watt + 64 + o4 * 4 + 3);
    }

    float4* h4 = reinterpret_cast<float4*>(g_h) + n * 16;
#pragma unroll
    for (int o4 = 0; o4 < 16; o4++) h4[o4] = acc[o4];
    g_sI[n] = sI;
    g_sJ[n] = sJ;
}

// ================= edge pass: GEMM -> ea, logit =================
template <bool EHEAD>
__device__ __forceinline__ void ea_epilogue(
    float4 (&acc)[16], int e,
    const int* __restrict__ ei, const int* __restrict__ etype,
    const float* sWe, const float* sEteW,
    float* __restrict__ eaout,
    const float* sWec, const float* sBec, float* __restrict__ eout)
{
    int t = etype[e];
    float pre = 0.f, eo = 0.f;
    const float* wec = sWec + t * 64;
    float4* out4 = reinterpret_cast<float4*>(eaout) + (long)e * 16;
#pragma unroll
    for (int o4 = 0; o4 < 16; o4++) {
        float4 a = acc[o4];
        a.x = lrelu(a.x); a.y = lrelu(a.y); a.z = lrelu(a.z); a.w = lrelu(a.w);
        pre += a.x * sWe[o4 * 4]     + a.y * sWe[o4 * 4 + 1]
             + a.z * sWe[o4 * 4 + 2] + a.w * sWe[o4 * 4 + 3];
        if (EHEAD) {
            eo += fmaxf(a.x, 0.f) * wec[o4 * 4]     + fmaxf(a.y, 0.f) * wec[o4 * 4 + 1]
                + fmaxf(a.z, 0.f) * wec[o4 * 4 + 2] + fmaxf(a.w, 0.f) * wec[o4 * 4 + 3];
        }
        out4[o4] = a;
    }
    if (EHEAD) eout[e] = eo + sBec[t];

    int src = ei[e];
    int dst = ei[E_ + e];
    g_logit[e] = lrelu(g_sI[dst] + g_sJ[src] + pre + sEteW[t]);
}

template <int IN, bool RELU, bool EHEAD>
__global__ void __launch_bounds__(128)
edge_ea_kernel(const float* __restrict__ ein, const int* __restrict__ ei,
               const int* __restrict__ etype, const float* __restrict__ Wea,
               const float* __restrict__ Watt, const float* __restrict__ Ete,
               float* __restrict__ eaout,
               const float* __restrict__ Wec, const float* __restrict__ bec,
               float* __restrict__ eout) {
    __shared__ float4 sW[IN * 16];
    __shared__ float  sWe[64];
    __shared__ float  sEteW[ET_];
    __shared__ float  sWec[ET_ * 64];
    __shared__ float  sBec[ET_];
    for (int i = threadIdx.x; i < IN * 16; i += blockDim.x)
        sW[i] = reinterpret_cast<const float4*>(Wea)[i];
    if (threadIdx.x < 64) sWe[threadIdx.x] = Watt[132 + threadIdx.x];
    if (threadIdx.x < ET_) {
        float a = 0.f;
#pragma unroll
        for (int j = 0; j < 4; j++) a += lrelu(Ete[threadIdx.x * 4 + j]) * Watt[128 + j];
        sEteW[threadIdx.x] = a;
    }
    if (EHEAD) {
        for (int i = threadIdx.x; i < ET_ * 64; i += blockDim.x) sWec[i] = Wec[i];
        if (threadIdx.x < ET_) sBec[threadIdx.x] = bec[threadIdx.x];
    }
    __syncthreads();

    int e0 = blockIdx.x * blockDim.x + threadIdx.x;   // < HALF_E by grid sizing
    int e1 = e0 + HALF_E;

    float4 acc0[16], acc1[16];
#pragma unroll
    for (int o4 = 0; o4 < 16; o4++) {
        acc0[o4] = make_float4(0.f, 0.f, 0.f, 0.f);
        acc1[o4] = make_float4(0.f, 0.f, 0.f, 0.f);
    }

    const float4* in4 = reinterpret_cast<const float4*>(ein);
    const float4* r0 = in4 + (long)e0 * (IN / 4);
    const float4* r1 = in4 + (long)e1 * (IN / 4);
#pragma unroll 1
    for (int kc = 0; kc < IN / 4; kc++) {
        float4 v0 = r0[kc];
        float4 v1 = r1[kc];
        if (RELU) {
            v0.x = fmaxf(v0.x, 0.f); v0.y = fmaxf(v0.y, 0.f);
            v0.z = fmaxf(v0.z, 0.f); v0.w = fmaxf(v0.w, 0.f);
            v1.x = fmaxf(v1.x, 0.f); v1.y = fmaxf(v1.y, 0.f);
            v1.z = fmaxf(v1.z, 0.f); v1.w = fmaxf(v1.w, 0.f);
        }
        float a0[4] = {v0.x, v0.y, v0.z, v0.w};
        float a1[4] = {v1.x, v1.y, v1.z, v1.w};
#pragma unroll
        for (int j = 0; j < 4; j++) {
            float u0 = a0[j], u1 = a1[j];
            const float4* wr = sW + (kc * 4 + j) * 16;
#pragma unroll
            for (int o4 = 0; o4 < 16; o4++) {
                float4 w = wr[o4];
                acc0[o4].x += u0 * w.x; acc0[o4].y += u0 * w.y;
                acc0[o4].z += u0 * w.z; acc0[o4].w += u0 * w.w;
                acc1[o4].x += u1 * w.x; acc1[o4].y += u1 * w.y;
                acc1[o4].z += u1 * w.z; acc1[o4].w += u1 * w.w;
            }
        }
    }

    ea_epilogue<EHEAD>(acc0, e0, ei, etype, sWe, sEteW, eaout, sWec, sBec, eout);
    ea_epilogue<EHEAD>(acc1, e1, ei, etype, sWe, sEteW, eaout, sWec, sBec, eout);
}

// ================= CSR gather: per-node softmax aggregation =================
// one warp per node; lanes 0-15 accumulate s1 (ex*ea), lanes 16-31 s2 (ex*h[src])
__global__ void __launch_bounds__(256)
gather_kernel(const float* __restrict__ ea, const int* __restrict__ ei) {
    int gw = (blockIdx.x * blockDim.x + threadIdx.x) >> 5;
    int lane = threadIdx.x & 31;
    if (gw >= N_) return;

    int beg = g_off[gw];
    int end = g_off[gw + 1];

    const float4* ea4 = reinterpret_cast<const float4*>(ea);
    const float4* h4  = reinterpret_cast<const float4*>(g_h);

    float4 acc = make_float4(0.f, 0.f, 0.f, 0.f);
    float sumex = 0.f;

    for (int i = beg; i < end; i++) {
        int e = g_perm[i];
        float ex = expf(g_logit[e]);
        sumex += ex;
        float4 v;
        if (lane < 16) {
            v = ea4[(long)e * 16 + lane];
        } else {
            int src = ei[e];
            v = h4[(long)src * 16 + (lane - 16)];
        }
        acc.x += ex * v.x; acc.y += ex * v.y;
        acc.z += ex * v.z; acc.w += ex * v.w;
    }

    if (lane < 16) reinterpret_cast<float4*>(g_s1)[(long)gw * 16 + lane] = acc;
    else           reinterpret_cast<float4*>(g_s2)[(long)gw * 16 + (lane - 16)] = acc;
    if (lane == 0) g_sum[gw] = sumex;
}

// ================= finish: out = (s2@Wlin[:H] + s1@Wlin[H:]) / sum ==========
template <bool HEAD>
__global__ void __launch_bounds__(128)
finish_kernel(const float* __restrict__ Wlin, const int* __restrict__ ntype,
              const float* __restrict__ Wnc, const float* __restrict__ bnc,
              float* __restrict__ dout) {
    __shared__ float4 sW[128 * 16];   // 32KB: full (2H x H) Wlin
    for (int i = threadIdx.x; i < 128 * 16; i += blockDim.x)
        sW[i] = reinterpret_cast<const float4*>(Wlin)[i];
    __syncthreads();

    int n = blockIdx.x * blockDim.x + threadIdx.x;
    if (n >= N_) return;

    float4 acc[16];
#pragma unroll
    for (int o4 = 0; o4 < 16; o4++) acc[o4] = make_float4(0.f, 0.f, 0.f, 0.f);

    const float4* r2 = reinterpret_cast<const float4*>(g_s2) + n * 16;  // k 0..63
    const float4* r1 = reinterpret_cast<const float4*>(g_s1) + n * 16;  // k 64..127
#pragma unroll 1
    for (int kc = 0; kc < 16; kc++) {
        float4 v4 = r2[kc];
        float vv[4] = {v4.x, v4.y, v4.z, v4.w};
#pragma unroll
        for (int j = 0; j < 4; j++) {
            float v = vv[j];
            const float4* wr = sW + (kc * 4 + j) * 16;
#pragma unroll
            for (int o4 = 0; o4 < 16; o4++) {
                float4 w = wr[o4];
                acc[o4].x += v * w.x; acc[o4].y += v * w.y;
                acc[o4].z += v * w.z; acc[o4].w += v * w.w;
            }
        }
    }
#pragma unroll 1
    for (int kc = 0; kc < 16; kc++) {
        float4 v4 = r1[kc];
        float vv[4] = {v4.x, v4.y, v4.z, v4.w};
#pragma unroll
        for (int j = 0; j < 4; j++) {
            float v = vv[j];
            const float4* wr = sW + (64 + kc * 4 + j) * 16;
#pragma unroll
            for (int o4 = 0; o4 < 16; o4++) {
                float4 w = wr[o4];
                acc[o4].x += v * w.x; acc[o4].y += v * w.y;
                acc[o4].z += v * w.z; acc[o4].w += v * w.w;
            }
        }
    }

    float inv = 1.f / (g_sum[n] + 1e-16f);
    if (!HEAD) {
        float4* out4 = reinterpret_cast<float4*>(g_out) + n * 16;
#pragma unroll
        for (int o4 = 0; o4 < 16; o4++) {
            float4 a = acc[o4];
            a.x *= inv; a.y *= inv; a.z *= inv; a.w *= inv;
            out4[o4] = a;
        }
    } else {
        int t = ntype[n];
        const float* w = Wnc + t * 64;
        float head = bnc[t];
#pragma unroll
        for (int o4 = 0; o4 < 16; o4++) {
            float4 a = acc[o4];
            head += fmaxf(a.x * inv, 0.f) * __ldg(w + o4 * 4)
                  + fmaxf(a.y * inv, 0.f) * __ldg(w + o4 * 4 + 1)
                  + fmaxf(a.z * inv, 0.f) * __ldg(w + o4 * 4 + 2)
                  + fmaxf(a.w * inv, 0.f) * __ldg(w + o4 * 4 + 3);
        }
        dout[n] = head;
    }
}

// ================= launcher =================
extern "C" void kernel_launch(void* const* d_in, const int* in_sizes, int n_in,
                              void* d_out, int out_size) {
    const float* x     = (const float*)d_in[0];
    const int*   ei    = (const int*)d_in[1];
    const int*   ntype = (const int*)d_in[2];
    const int*   etype = (const int*)d_in[3];
    const float* eattr = (const float*)d_in[4];

    const float* Whl[3]  = {(const float*)d_in[5],  (const float*)d_in[11], (const float*)d_in[17]};
    const float* bhl[3]  = {(const float*)d_in[6],  (const float*)d_in[12], (const float*)d_in[18]};
    const float* Ete[3]  = {(const float*)d_in[7],  (const float*)d_in[13], (const float*)d_in[19]};
    const float* Wea[3]  = {(const float*)d_in[8],  (const float*)d_in[14], (const float*)d_in[20]};
    const float* Watt[3] = {(const float*)d_in[9],  (const float*)d_in[15], (const float*)d_in[21]};
    const float* Wlin[3] = {(const float*)d_in[10], (const float*)d_in[16], (const float*)d_in[22]};
    const float* Wnc = (const float*)d_in[23];
    const float* bnc = (const float*)d_in[24];
    const float* Wec = (const float*)d_in[25];
    const float* bec = (const float*)d_in[26];

    float *e0, *e1, *ea3, *outBuf;
    cudaGetSymbolAddress((void**)&e0, g_e0);
    cudaGetSymbolAddress((void**)&e1, g_e1);
    cudaGetSymbolAddress((void**)&ea3, g_ea3);
    cudaGetSymbolAddress((void**)&outBuf, g_out);

    const int nodeBlocks   = (N_ + 127) / 128;
    const int eaBlocks     = HALF_E / 128;          // 3125
    const int edgeBlocks   = (E_ + 255) / 256;      // 3125
    const int gatherBlocks = (N_ * 32) / 256;       // 6250

    float* doutN = (float*)d_out;        // node head [0, N)
    float* doutE = (float*)d_out + N_;   // edge head [N, N+E)

    // ---- CSR build (graph identical for all 3 layers) ----
    zero_deg_kernel<<<(N_ + 255) / 256, 256>>>();
    hist_kernel<<<edgeBlocks, 256>>>(ei);
    scan_kernel<<<1, 1024>>>();
    scatter_perm_kernel<<<edgeBlocks, 256>>>(ei);

    // ---- layer 1 ----
    node_kernel<false><<<nodeBlocks, 128>>>(x, ntype, Whl[0], bhl[0], Watt[0]);
    edge_ea_kernel<FE_, false, false><<<eaBlocks, 128>>>(
        eattr, ei, etype, Wea[0], Watt[0], Ete[0], e0, nullptr, nullptr, nullptr);
    gather_kernel<<<gatherBlocks, 256>>>(e0, ei);
    finish_kernel<false><<<nodeBlocks, 128>>>(Wlin[0], nullptr, nullptr, nullptr, nullptr);

    // ---- layer 2 ----
    node_kernel<true><<<nodeBlocks, 128>>>(outBuf, ntype, Whl[1], bhl[1], Watt[1]);
    edge_ea_kernel<H_, true, false><<<eaBlocks, 128>>>(
        e0, ei, etype, Wea[1], Watt[1], Ete[1], e1, nullptr, nullptr, nullptr);
    gather_kernel<<<gatherBlocks, 256>>>(e1, ei);
    finish_kernel<false><<<nodeBlocks, 128>>>(Wlin[1], nullptr, nullptr, nullptr, nullptr);

    // ---- layer 3 ----
    node_kernel<true><<<nodeBlocks, 128>>>(outBuf, ntype, Whl[2], bhl[2], Watt[2]);
    edge_ea_kernel<H_, true, true><<<eaBlocks, 128>>>(
        e1, ei, etype, Wea[2], Watt[2], Ete[2], ea3, Wec, bec, doutE);
    gather_kernel<<<gatherBlocks, 256>>>(ea3, ei);
    finish_kernel<true><<<nodeBlocks, 128>>>(Wlin[2], ntype, Wnc, bnc, doutN);
}

// round 6
// speedup vs baseline: 1.3029x; 1.1720x over previous
#include <cuda_runtime.h>
#include <math.h>
#include <stdint.h>

#define N_   50000
#define E_   800000
#define H_   64
#define FE_  32
#define NT_  3
#define ET_  4
#define NEG_ 0.2f

// ---------------- device scratch ----------------
__device__ __align__(16) float g_e0[E_ * H_];     // ea layer1 (CSR order)
__device__ __align__(16) float g_e1[E_ * H_];     // ea layer2 (CSR order)
__device__ __align__(16) float g_ea3[E_ * H_];    // ea layer3 (CSR order)
__device__ __align__(16) float g_pattr[E_ * FE_]; // permuted edge_attr
__device__ __align__(16) float g_h [N_ * H_];
__device__ __align__(16) float g_s1[N_ * H_];
__device__ __align__(16) float g_s2[N_ * H_];
__device__ __align__(16) float g_out[N_ * H_];
__device__ float g_sI[N_];
__device__ float g_sJ[N_];
__device__ float g_sum[N_];
__device__ float g_logit[E_];                     // CSR order
// CSR
__device__ int g_deg[N_];
__device__ int g_off[N_ + 1];
__device__ int g_cur[N_];
__device__ int g_perm[E_];      // CSR pos -> original edge id
__device__ int g_psrc[E_];
__device__ int g_pdst[E_];
__device__ int g_petype[E_];

// ---------------- helpers ----------------
__device__ __forceinline__ float lrelu(float x) { return x > 0.f ? x : NEG_ * x; }

__device__ __forceinline__ uint32_t f2tf(float f) {
    uint32_t r;
    asm("cvt.rna.tf32.f32 %0, %1;" : "=r"(r) : "f"(f));
    return r;
}

__device__ __forceinline__ void mma_tf32(float (&c)[4],
                                         uint32_t a0, uint32_t a1, uint32_t a2, uint32_t a3,
                                         uint32_t b0, uint32_t b1) {
    asm volatile(
        "mma.sync.aligned.m16n8k8.row.col.f32.tf32.tf32.f32 "
        "{%0,%1,%2,%3}, {%4,%5,%6,%7}, {%8,%9}, {%0,%1,%2,%3};"
        : "+f"(c[0]), "+f"(c[1]), "+f"(c[2]), "+f"(c[3])
        : "r"(a0), "r"(a1), "r"(a2), "r"(a3), "r"(b0), "r"(b1));
}

// ================= CSR construction =================
__global__ void zero_deg_kernel() {
    int i = blockIdx.x * blockDim.x + threadIdx.x;
    if (i < N_) g_deg[i] = 0;
}

__global__ void hist_kernel(const int* __restrict__ ei) {
    int e = blockIdx.x * blockDim.x + threadIdx.x;
    if (e < E_) atomicAdd(&g_deg[ei[E_ + e]], 1);
}

__global__ void scan_kernel() {
    __shared__ int warpsum[32];
    __shared__ int s_carry;
    int tid = threadIdx.x;
    int lane = tid & 31, wid = tid >> 5;
    if (tid == 0) s_carry = 0;
    __syncthreads();
    for (int base = 0; base < N_; base += 1024) {
        int i = base + tid;
        int v = (i < N_) ? g_deg[i] : 0;
        int incl = v;
#pragma unroll
        for (int d = 1; d < 32; d <<= 1) {
            int t = __shfl_up_sync(0xFFFFFFFFu, incl, d);
            if (lane >= d) incl += t;
        }
        if (lane == 31) warpsum[wid] = incl;
        __syncthreads();
        if (wid == 0) {
            int w = warpsum[lane];
#pragma unroll
            for (int d = 1; d < 32; d <<= 1) {
                int t = __shfl_up_sync(0xFFFFFFFFu, w, d);
                if (lane >= d) w += t;
            }
            warpsum[lane] = w;
        }
        __syncthreads();
        int off = s_carry + (wid > 0 ? warpsum[wid - 1] : 0);
        int excl = off + incl - v;
        if (i < N_) { g_off[i] = excl; g_cur[i] = excl; }
        __syncthreads();
        if (tid == 0) s_carry += warpsum[31];
        __syncthreads();
    }
    if (tid == 0) g_off[N_] = s_carry;
}

__global__ void scatter_perm_kernel(const int* __restrict__ ei) {
    int e = blockIdx.x * blockDim.x + threadIdx.x;
    if (e >= E_) return;
    int pos = atomicAdd(&g_cur[ei[E_ + e]], 1);
    g_perm[pos] = e;
}

__global__ void perm_meta_kernel(const int* __restrict__ ei, const int* __restrict__ etype) {
    int i = blockIdx.x * blockDim.x + threadIdx.x;
    if (i >= E_) return;
    int o = g_perm[i];
    g_psrc[i]   = ei[o];
    g_pdst[i]   = ei[E_ + o];
    g_petype[i] = etype[o];
}

__global__ void perm_attr_kernel(const float* __restrict__ eattr) {
    int idx = blockIdx.x * blockDim.x + threadIdx.x;   // E_*8 threads
    int i = idx >> 3, j = idx & 7;
    if (i >= E_) return;
    int o = g_perm[i];
    reinterpret_cast<float4*>(g_pattr)[(long)i * 8 + j] =
        reinterpret_cast<const float4*>(eattr)[(long)o * 8 + j];
}

// ================= node pass =================
template <bool RELU>
__global__ void __launch_bounds__(128)
node_kernel(const float* __restrict__ xin, const int* __restrict__ ntype,
            const float* __restrict__ Whl, const float* __restrict__ bhl,
            const float* __restrict__ Watt) {
    __shared__ float4 sW[NT_ * H_ * 16];
    for (int i = threadIdx.x; i < NT_ * H_ * 16; i += blockDim.x)
        sW[i] = reinterpret_cast<const float4*>(Whl)[i];
    __syncthreads();

    int n = blockIdx.x * blockDim.x + threadIdx.x;
    if (n >= N_) return;
    int t = ntype[n];

    const float4* b4 = reinterpret_cast<const float4*>(bhl) + t * 16;
    float4 acc[16];
#pragma unroll
    for (int o4 = 0; o4 < 16; o4++) acc[o4] = __ldg(b4 + o4);

    const float4* x4 = reinterpret_cast<const float4*>(xin) + n * 16;
    const float4* W4 = sW + t * 1024;
#pragma unroll 1
    for (int kc = 0; kc < 16; kc++) {
        float4 v4 = x4[kc];
        if (RELU) {
            v4.x = fmaxf(v4.x, 0.f); v4.y = fmaxf(v4.y, 0.f);
            v4.z = fmaxf(v4.z, 0.f); v4.w = fmaxf(v4.w, 0.f);
        }
        float vv[4] = {v4.x, v4.y, v4.z, v4.w};
#pragma unroll
        for (int j = 0; j < 4; j++) {
            float v = vv[j];
            const float4* wr = W4 + (kc * 4 + j) * 16;
#pragma unroll
            for (int o4 = 0; o4 < 16; o4++) {
                float4 w = wr[o4];
                acc[o4].x += v * w.x; acc[o4].y += v * w.y;
                acc[o4].z += v * w.z; acc[o4].w += v * w.w;
            }
        }
    }

    float sI = 0.f, sJ = 0.f;
#pragma unroll
    for (int o4 = 0; o4 < 16; o4++) {
        float4 a = acc[o4];
        sI += a.x * __ldg(Watt + o4 * 4)     + a.y * __ldg(Watt + o4 * 4 + 1)
            + a.z * __ldg(Watt + o4 * 4 + 2) + a.w * __ldg(Watt + o4 * 4 + 3);
        sJ += a.x * __ldg(Watt + 64 + o4 * 4)     + a.y * __ldg(Watt + 64 + o4 * 4 + 1)
            + a.z * __ldg(Watt + 64 + o4 * 4 + 2) + a.w * __ldg(Watt + 64 + o4 * 4 + 3);
    }

    float4* h4 = reinterpret_cast<float4*>(g_h) + n * 16;
#pragma unroll
    for (int o4 = 0; o4 < 16; o4++) h4[o4] = acc[o4];
    g_sI[n] = sI;
    g_sJ[n] = sJ;
}

// ================= edge pass: tf32 tensor-core GEMM + epilogue =================
// block = 256 threads = 8 warps; warp computes 16 edges x 64 outputs.
// All per-edge arrays are in CSR order.
template <int IN, bool RELU, bool EHEAD>
__global__ void __launch_bounds__(256)
edge_mma_kernel(const float* __restrict__ ein,
                const float* __restrict__ Wea,
                const float* __restrict__ Watt, const float* __restrict__ Ete,
                float* __restrict__ eaout,
                const float* __restrict__ Wec, const float* __restrict__ bec,
                float* __restrict__ eout) {
    constexpr int KB = IN / 8;
    __shared__ uint32_t sB[KB * 8 * 64];   // per-(kb,nb) fragments, lane-interleaved
    __shared__ float sWe[64];
    __shared__ float sEteW[ET_];
    __shared__ float sWec[ET_ * 64];
    __shared__ float sBec[ET_];

    int tid = threadIdx.x;
    for (int i = tid; i < KB * 8 * 64; i += 256) {
        int kbnb = i >> 6;
        int l    = (i >> 1) & 31;
        int half = i & 1;
        int kb = kbnb >> 3, nb = kbnb & 7;
        int k = kb * 8 + (l & 3) + half * 4;
        int n = nb * 8 + (l >> 2);
        sB[i] = f2tf(Wea[k * 64 + n]);
    }
    if (tid < 64) sWe[tid] = Watt[132 + tid];
    if (tid < ET_) {
        float a = 0.f;
#pragma unroll
        for (int j = 0; j < 4; j++) a += lrelu(Ete[tid * 4 + j]) * Watt[128 + j];
        sEteW[tid] = a;
    }
    if (EHEAD) {
        for (int i = tid; i < ET_ * 64; i += 256) sWec[i] = Wec[i];
        if (tid < ET_) sBec[tid] = bec[tid];
    }
    __syncthreads();

    int warp = tid >> 5, lane = tid & 31;
    int g  = lane >> 2;       // row group 0..7
    int tg = lane & 3;        // thread-in-group
    int e16 = blockIdx.x * 128 + warp * 16;

    float c[8][4];
#pragma unroll
    for (int nb = 0; nb < 8; nb++) {
        c[nb][0] = 0.f; c[nb][1] = 0.f; c[nb][2] = 0.f; c[nb][3] = 0.f;
    }

    const float* A0 = ein + (long)(e16 + g) * IN;
    const float* A1 = ein + (long)(e16 + g + 8) * IN;
    const uint2* bf = reinterpret_cast<const uint2*>(sB);

#pragma unroll
    for (int kb = 0; kb < KB; kb++) {
        float f0 = A0[kb * 8 + tg];
        float f1 = A1[kb * 8 + tg];
        float f2 = A0[kb * 8 + tg + 4];
        float f3 = A1[kb * 8 + tg + 4];
        if (RELU) {
            f0 = fmaxf(f0, 0.f); f1 = fmaxf(f1, 0.f);
            f2 = fmaxf(f2, 0.f); f3 = fmaxf(f3, 0.f);
        }
        uint32_t a0 = f2tf(f0), a1 = f2tf(f1), a2 = f2tf(f2), a3 = f2tf(f3);
#pragma unroll
        for (int nb = 0; nb < 8; nb++) {
            uint2 b = bf[(kb * 8 + nb) * 32 + lane];
            mma_tf32(c[nb], a0, a1, a2, a3, b.x, b.y);
        }
    }

    // ---- epilogue ----
    int er0 = e16 + g;
    int er1 = e16 + g + 8;
    int t0 = g_petype[er0];
    int t1 = g_petype[er1];

    float pre0 = 0.f, pre1 = 0.f, eo0 = 0.f, eo1 = 0.f;
#pragma unroll
    for (int nb = 0; nb < 8; nb++) {
        int col = nb * 8 + tg * 2;
        float x0 = lrelu(c[nb][0]), x1 = lrelu(c[nb][1]);
        float x2 = lrelu(c[nb][2]), x3 = lrelu(c[nb][3]);
        pre0 += x0 * sWe[col] + x1 * sWe[col + 1];
        pre1 += x2 * sWe[col] + x3 * sWe[col + 1];
        if (EHEAD) {
            eo0 += fmaxf(x0, 0.f) * sWec[t0 * 64 + col] + fmaxf(x1, 0.f) * sWec[t0 * 64 + col + 1];
            eo1 += fmaxf(x2, 0.f) * sWec[t1 * 64 + col] + fmaxf(x3, 0.f) * sWec[t1 * 64 + col + 1];
        }
        *reinterpret_cast<float2*>(eaout + (long)er0 * 64 + col) = make_float2(x0, x1);
        *reinterpret_cast<float2*>(eaout + (long)er1 * 64 + col) = make_float2(x2, x3);
    }
    pre0 += __shfl_xor_sync(0xFFFFFFFFu, pre0, 1);
    pre0 += __shfl_xor_sync(0xFFFFFFFFu, pre0, 2);
    pre1 += __shfl_xor_sync(0xFFFFFFFFu, pre1, 1);
    pre1 += __shfl_xor_sync(0xFFFFFFFFu, pre1, 2);
    if (EHEAD) {
        eo0 += __shfl_xor_sync(0xFFFFFFFFu, eo0, 1);
        eo0 += __shfl_xor_sync(0xFFFFFFFFu, eo0, 2);
        eo1 += __shfl_xor_sync(0xFFFFFFFFu, eo1, 1);
        eo1 += __shfl_xor_sync(0xFFFFFFFFu, eo1, 2);
    }

    if (tg == 0) {
        int s0 = g_psrc[er0], d0 = g_pdst[er0];
        int s1 = g_psrc[er1], d1 = g_pdst[er1];
        g_logit[er0] = lrelu(g_sI[d0] + g_sJ[s0] + pre0 + sEteW[t0]);
        g_logit[er1] = lrelu(g_sI[d1] + g_sJ[s1] + pre1 + sEteW[t1]);
        if (EHEAD) {
            eout[g_perm[er0]] = eo0 + sBec[t0];
            eout[g_perm[er1]] = eo1 + sBec[t1];
        }
    }
}

// ================= gather: per-node softmax aggregation (sequential CSR) ====
__global__ void __launch_bounds__(256)
gather_kernel(const float* __restrict__ ea) {
    int gw = (blockIdx.x * blockDim.x + threadIdx.x) >> 5;
    int lane = threadIdx.x & 31;
    if (gw >= N_) return;

    int beg = g_off[gw];
    int end = g_off[gw + 1];

    const float4* ea4 = reinterpret_cast<const float4*>(ea);
    const float4* h4  = reinterpret_cast<const float4*>(g_h);

    float4 acc = make_float4(0.f, 0.f, 0.f, 0.f);
    float sumex = 0.f;

    for (int i = beg; i < end; i++) {
        float ex = 0.f;
        if (lane == 0) ex = expf(g_logit[i]);
        ex = __shfl_sync(0xFFFFFFFFu, ex, 0);
        sumex += ex;
        float4 v;
        if (lane < 16) {
            v = ea4[(long)i * 16 + lane];
        } else {
            int src = g_psrc[i];
            v = h4[(long)src * 16 + (lane - 16)];
        }
        acc.x += ex * v.x; acc.y += ex * v.y;
        acc.z += ex * v.z; acc.w += ex * v.w;
    }

    if (lane < 16) reinterpret_cast<float4*>(g_s1)[(long)gw * 16 + lane] = acc;
    else           reinterpret_cast<float4*>(g_s2)[(long)gw * 16 + (lane - 16)] = acc;
    if (lane == 0) g_sum[gw] = sumex;
}

// ================= finish: out = (s2@Wlin[:H] + s1@Wlin[H:]) / sum ==========
template <bool HEAD>
__global__ void __launch_bounds__(128)
finish_kernel(const float* __restrict__ Wlin, const int* __restrict__ ntype,
              const float* __restrict__ Wnc, const float* __restrict__ bnc,
              float* __restrict__ dout) {
    __shared__ float4 sW[128 * 16];
    for (int i = threadIdx.x; i < 128 * 16; i += blockDim.x)
        sW[i] = reinterpret_cast<const float4*>(Wlin)[i];
    __syncthreads();

    int n = blockIdx.x * blockDim.x + threadIdx.x;
    if (n >= N_) return;

    float4 acc[16];
#pragma unroll
    for (int o4 = 0; o4 < 16; o4++) acc[o4] = make_float4(0.f, 0.f, 0.f, 0.f);

    const float4* r2 = reinterpret_cast<const float4*>(g_s2) + n * 16;
    const float4* r1 = reinterpret_cast<const float4*>(g_s1) + n * 16;
#pragma unroll 1
    for (int kc = 0; kc < 16; kc++) {
        float4 v4 = r2[kc];
        float vv[4] = {v4.x, v4.y, v4.z, v4.w};
#pragma unroll
        for (int j = 0; j < 4; j++) {
            float v = vv[j];
            const float4* wr = sW + (kc * 4 + j) * 16;
#pragma unroll
            for (int o4 = 0; o4 < 16; o4++) {
                float4 w = wr[o4];
                acc[o4].x += v * w.x; acc[o4].y += v * w.y;
                acc[o4].z += v * w.z; acc[o4].w += v * w.w;
            }
        }
    }
#pragma unroll 1
    for (int kc = 0; kc < 16; kc++) {
        float4 v4 = r1[kc];
        float vv[4] = {v4.x, v4.y, v4.z, v4.w};
#pragma unroll
        for (int j = 0; j < 4; j++) {
            float v = vv[j];
            const float4* wr = sW + (64 + kc * 4 + j) * 16;
#pragma unroll
            for (int o4 = 0; o4 < 16; o4++) {
                float4 w = wr[o4];
                acc[o4].x += v * w.x; acc[o4].y += v * w.y;
                acc[o4].z += v * w.z; acc[o4].w += v * w.w;
            }
        }
    }

    float inv = 1.f / (g_sum[n] + 1e-16f);
    if (!HEAD) {
        float4* out4 = reinterpret_cast<float4*>(g_out) + n * 16;
#pragma unroll
        for (int o4 = 0; o4 < 16; o4++) {
            float4 a = acc[o4];
            a.x *= inv; a.y *= inv; a.z *= inv; a.w *= inv;
            out4[o4] = a;
        }
    } else {
        int t = ntype[n];
        const float* w = Wnc + t * 64;
        float head = bnc[t];
#pragma unroll
        for (int o4 = 0; o4 < 16; o4++) {
            float4 a = acc[o4];
            head += fmaxf(a.x * inv, 0.f) * __ldg(w + o4 * 4)
                  + fmaxf(a.y * inv, 0.f) * __ldg(w + o4 * 4 + 1)
                  + fmaxf(a.z * inv, 0.f) * __ldg(w + o4 * 4 + 2)
                  + fmaxf(a.w * inv, 0.f) * __ldg(w + o4 * 4 + 3);
        }
        dout[n] = head;
    }
}

// ================= launcher =================
extern "C" void kernel_launch(void* const* d_in, const int* in_sizes, int n_in,
                              void* d_out, int out_size) {
    const float* x     = (const float*)d_in[0];
    const int*   ei    = (const int*)d_in[1];
    const int*   ntype = (const int*)d_in[2];
    const int*   etype = (const int*)d_in[3];
    const float* eattr = (const float*)d_in[4];

    const float* Whl[3]  = {(const float*)d_in[5],  (const float*)d_in[11], (const float*)d_in[17]};
    const float* bhl[3]  = {(const float*)d_in[6],  (const float*)d_in[12], (const float*)d_in[18]};
    const float* Ete[3]  = {(const float*)d_in[7],  (const float*)d_in[13], (const float*)d_in[19]};
    const float* Wea[3]  = {(const float*)d_in[8],  (const float*)d_in[14], (const float*)d_in[20]};
    const float* Watt[3] = {(const float*)d_in[9],  (const float*)d_in[15], (const float*)d_in[21]};
    const float* Wlin[3] = {(const float*)d_in[10], (const float*)d_in[16], (const float*)d_in[22]};
    const float* Wnc = (const float*)d_in[23];
    const float* bnc = (const float*)d_in[24];
    const float* Wec = (const float*)d_in[25];
    const float* bec = (const float*)d_in[26];

    float *e0, *e1, *ea3, *pattr, *outBuf;
    cudaGetSymbolAddress((void**)&e0, g_e0);
    cudaGetSymbolAddress((void**)&e1, g_e1);
    cudaGetSymbolAddress((void**)&ea3, g_ea3);
    cudaGetSymbolAddress((void**)&pattr, g_pattr);
    cudaGetSymbolAddress((void**)&outBuf, g_out);

    const int nodeBlocks   = (N_ + 127) / 128;
    const int mmaBlocks    = E_ / 128;              // 6250
    const int edgeBlocks   = (E_ + 255) / 256;
    const int gatherBlocks = (N_ * 32 + 255) / 256;

    float* doutN = (float*)d_out;
    float* doutE = (float*)d_out + N_;

    // ---- CSR build + permutation (graph identical for all layers) ----
    zero_deg_kernel<<<(N_ + 255) / 256, 256>>>();
    hist_kernel<<<edgeBlocks, 256>>>(ei);
    scan_kernel<<<1, 1024>>>();
    scatter_perm_kernel<<<edgeBlocks, 256>>>(ei);
    perm_meta_kernel<<<edgeBlocks, 256>>>(ei, etype);
    perm_attr_kernel<<<(E_ * 8 + 255) / 256, 256>>>(eattr);

    // ---- layer 1 ----
    node_kernel<false><<<nodeBlocks, 128>>>(x, ntype, Whl[0], bhl[0], Watt[0]);
    edge_mma_kernel<FE_, false, false><<<mmaBlocks, 256>>>(
        pattr, Wea[0], Watt[0], Ete[0], e0, nullptr, nullptr, nullptr);
    gather_kernel<<<gatherBlocks, 256>>>(e0);
    finish_kernel<false><<<nodeBlocks, 128>>>(Wlin[0], nullptr, nullptr, nullptr, nullptr);

    // ---- layer 2 ----
    node_kernel<true><<<nodeBlocks, 128>>>(outBuf, ntype, Whl[1], bhl[1], Watt[1]);
    edge_mma_kernel<H_, true, false><<<mmaBlocks, 256>>>(
        e0, Wea[1], Watt[1], Ete[1], e1, nullptr, nullptr, nullptr);
    gather_kernel<<<gatherBlocks, 256>>>(e1);
    finish_kernel<false><<<nodeBlocks, 128>>>(Wlin[1], nullptr, nullptr, nullptr, nullptr);

    // ---- layer 3 ----
    node_kernel<true><<<nodeBlocks, 128>>>(outBuf, ntype, Whl[2], bhl[2], Watt[2]);
    edge_mma_kernel<H_, true, true><<<mmaBlocks, 256>>>(
        e1, Wea[2], Watt[2], Ete[2], ea3, Wec, bec, doutE);
    gather_kernel<<<gatherBlocks, 256>>>(ea3);
    finish_kernel<true><<<nodeBlocks, 128>>>(Wlin[2], ntype, Wnc, bnc, doutN);
}

// round 7
// speedup vs baseline: 1.4496x; 1.1126x over previous
#include <cuda_runtime.h>
#include <cuda_fp16.h>
#include <math.h>
#include <stdint.h>

#define N_   50000
#define E_   800000
#define H_   64
#define FE_  32
#define NT_  3
#define ET_  4
#define NEG_ 0.2f

// ---------------- device scratch ----------------
__device__ __align__(16) __half g_e0[E_ * H_];     // ea layer1 (CSR order, fp16)
__device__ __align__(16) __half g_e1[E_ * H_];     // ea layer2
__device__ __align__(16) __half g_ea3[E_ * H_];    // ea layer3
__device__ __align__(16) __half g_pattr[E_ * FE_]; // permuted edge_attr (fp16)
__device__ __align__(16) float g_h [N_ * H_];
__device__ __align__(16) float g_out[N_ * H_];
__device__ float g_sI[N_];
__device__ float g_sJ[N_];
__device__ float g_logit[E_];                      // CSR order
// CSR
__device__ int g_deg[N_];
__device__ int g_off[N_ + 1];
__device__ int g_cur[N_];
__device__ int g_perm[E_];
__device__ int g_psrc[E_];
__device__ int g_pdst[E_];
__device__ int g_petype[E_];

// ---------------- helpers ----------------
__device__ __forceinline__ float lrelu(float x) { return x > 0.f ? x : NEG_ * x; }

__device__ __forceinline__ void mma_f16(float (&c)[4],
                                        uint32_t a0, uint32_t a1, uint32_t a2, uint32_t a3,
                                        uint32_t b0, uint32_t b1) {
    asm volatile(
        "mma.sync.aligned.m16n8k16.row.col.f32.f16.f16.f32 "
        "{%0,%1,%2,%3}, {%4,%5,%6,%7}, {%8,%9}, {%0,%1,%2,%3};"
        : "+f"(c[0]), "+f"(c[1]), "+f"(c[2]), "+f"(c[3])
        : "r"(a0), "r"(a1), "r"(a2), "r"(a3), "r"(b0), "r"(b1));
}

__device__ __forceinline__ uint32_t relu2(uint32_t u) {
    __half2 v = *reinterpret_cast<__half2*>(&u);
    __half2 z = __float2half2_rn(0.f);
    v = __hmax2(v, z);
    return *reinterpret_cast<uint32_t*>(&v);
}

__device__ __forceinline__ uint32_t pack_h2(float a, float b) {
    __half2 h = __floats2half2_rn(a, b);
    return *reinterpret_cast<uint32_t*>(&h);
}

// ================= CSR construction =================
__global__ void zero_deg_kernel() {
    int i = blockIdx.x * blockDim.x + threadIdx.x;
    if (i < N_) g_deg[i] = 0;
}

__global__ void hist_kernel(const int* __restrict__ ei) {
    int e = blockIdx.x * blockDim.x + threadIdx.x;
    if (e < E_) atomicAdd(&g_deg[ei[E_ + e]], 1);
}

__global__ void scan_kernel() {
    __shared__ int warpsum[32];
    __shared__ int s_carry;
    int tid = threadIdx.x;
    int lane = tid & 31, wid = tid >> 5;
    if (tid == 0) s_carry = 0;
    __syncthreads();
    for (int base = 0; base < N_; base += 1024) {
        int i = base + tid;
        int v = (i < N_) ? g_deg[i] : 0;
        int incl = v;
#pragma unroll
        for (int d = 1; d < 32; d <<= 1) {
            int t = __shfl_up_sync(0xFFFFFFFFu, incl, d);
            if (lane >= d) incl += t;
        }
        if (lane == 31) warpsum[wid] = incl;
        __syncthreads();
        if (wid == 0) {
            int w = warpsum[lane];
#pragma unroll
            for (int d = 1; d < 32; d <<= 1) {
                int t = __shfl_up_sync(0xFFFFFFFFu, w, d);
                if (lane >= d) w += t;
            }
            warpsum[lane] = w;
        }
        __syncthreads();
        int off = s_carry + (wid > 0 ? warpsum[wid - 1] : 0);
        int excl = off + incl - v;
        if (i < N_) { g_off[i] = excl; g_cur[i] = excl; }
        __syncthreads();
        if (tid == 0) s_carry += warpsum[31];
        __syncthreads();
    }
    if (tid == 0) g_off[N_] = s_carry;
}

__global__ void scatter_perm_kernel(const int* __restrict__ ei) {
    int e = blockIdx.x * blockDim.x + threadIdx.x;
    if (e >= E_) return;
    int pos = atomicAdd(&g_cur[ei[E_ + e]], 1);
    g_perm[pos] = e;
}

__global__ void perm_meta_kernel(const int* __restrict__ ei, const int* __restrict__ etype) {
    int i = blockIdx.x * blockDim.x + threadIdx.x;
    if (i >= E_) return;
    int o = g_perm[i];
    g_psrc[i]   = ei[o];
    g_pdst[i]   = ei[E_ + o];
    g_petype[i] = etype[o];
}

// permute edge_attr and convert fp32 -> fp16; 4 threads per edge
__global__ void perm_attr_kernel(const float* __restrict__ eattr) {
    int idx = blockIdx.x * blockDim.x + threadIdx.x;
    int i = idx >> 2, t = idx & 3;
    if (i >= E_) return;
    int o = g_perm[i];
    const float4* src = reinterpret_cast<const float4*>(eattr + (size_t)o * FE_) + t * 2;
    float4 f0 = src[0], f1 = src[1];
    uint4 u;
    u.x = pack_h2(f0.x, f0.y); u.y = pack_h2(f0.z, f0.w);
    u.z = pack_h2(f1.x, f1.y); u.w = pack_h2(f1.z, f1.w);
    reinterpret_cast<uint4*>(g_pattr)[(size_t)i * 4 + t] = u;
}

// ================= node pass =================
template <bool RELU>
__global__ void __launch_bounds__(128)
node_kernel(const float* __restrict__ xin, const int* __restrict__ ntype,
            const float* __restrict__ Whl, const float* __restrict__ bhl,
            const float* __restrict__ Watt) {
    __shared__ float4 sW[NT_ * H_ * 16];
    for (int i = threadIdx.x; i < NT_ * H_ * 16; i += blockDim.x)
        sW[i] = reinterpret_cast<const float4*>(Whl)[i];
    __syncthreads();

    int n = blockIdx.x * blockDim.x + threadIdx.x;
    if (n >= N_) return;
    int t = ntype[n];

    const float4* b4 = reinterpret_cast<const float4*>(bhl) + t * 16;
    float4 acc[16];
#pragma unroll
    for (int o4 = 0; o4 < 16; o4++) acc[o4] = __ldg(b4 + o4);

    const float4* x4 = reinterpret_cast<const float4*>(xin) + n * 16;
    const float4* W4 = sW + t * 1024;
#pragma unroll 1
    for (int kc = 0; kc < 16; kc++) {
        float4 v4 = x4[kc];
        if (RELU) {
            v4.x = fmaxf(v4.x, 0.f); v4.y = fmaxf(v4.y, 0.f);
            v4.z = fmaxf(v4.z, 0.f); v4.w = fmaxf(v4.w, 0.f);
        }
        float vv[4] = {v4.x, v4.y, v4.z, v4.w};
#pragma unroll
        for (int j = 0; j < 4; j++) {
            float v = vv[j];
            const float4* wr = W4 + (kc * 4 + j) * 16;
#pragma unroll
            for (int o4 = 0; o4 < 16; o4++) {
                float4 w = wr[o4];
                acc[o4].x += v * w.x; acc[o4].y += v * w.y;
                acc[o4].z += v * w.z; acc[o4].w += v * w.w;
            }
        }
    }

    float sI = 0.f, sJ = 0.f;
#pragma unroll
    for (int o4 = 0; o4 < 16; o4++) {
        float4 a = acc[o4];
        sI += a.x * __ldg(Watt + o4 * 4)     + a.y * __ldg(Watt + o4 * 4 + 1)
            + a.z * __ldg(Watt + o4 * 4 + 2) + a.w * __ldg(Watt + o4 * 4 + 3);
        sJ += a.x * __ldg(Watt + 64 + o4 * 4)     + a.y * __ldg(Watt + 64 + o4 * 4 + 1)
            + a.z * __ldg(Watt + 64 + o4 * 4 + 2) + a.w * __ldg(Watt + 64 + o4 * 4 + 3);
    }

    float4* h4 = reinterpret_cast<float4*>(g_h) + n * 16;
#pragma unroll
    for (int o4 = 0; o4 < 16; o4++) h4[o4] = acc[o4];
    g_sI[n] = sI;
    g_sJ[n] = sJ;
}

// ================= edge pass: fp16 tensor-core GEMM + epilogue =================
// block = 256 threads = 8 warps; warp computes 16 edges x 64 outputs.
template <int IN, bool RELU, bool EHEAD>
__global__ void __launch_bounds__(256)
edge_mma_kernel(const __half* __restrict__ ein,
                const float* __restrict__ Wea,
                const float* __restrict__ Watt, const float* __restrict__ Ete,
                __half* __restrict__ eaout,
                const float* __restrict__ Wec, const float* __restrict__ bec,
                float* __restrict__ eout) {
    constexpr int KB = IN / 16;
    __shared__ uint32_t sB[KB * 8 * 64];   // B fragments: (kb,nb) x lane x 2 regs
    __shared__ float sWe[64];
    __shared__ float sEteW[ET_];
    __shared__ float sWec[ET_ * 64];
    __shared__ float sBec[ET_];

    int tid = threadIdx.x;
    // fill B fragments (f16, col-major k16n8)
    for (int i = tid; i < KB * 8 * 64; i += 256) {
        int kbnb = i >> 6;
        int j = i & 63;
        int l = j >> 1;
        int hf = j & 1;
        int kb = kbnb >> 3, nb = kbnb & 7;
        int tg = l & 3, gg = l >> 2;
        int k0 = kb * 16 + 2 * tg + hf * 8;
        int n = nb * 8 + gg;
        sB[i] = pack_h2(Wea[k0 * 64 + n], Wea[(k0 + 1) * 64 + n]);
    }
    if (tid < 64) sWe[tid] = Watt[132 + tid];
    if (tid < ET_) {
        float a = 0.f;
#pragma unroll
        for (int j = 0; j < 4; j++) a += lrelu(Ete[tid * 4 + j]) * Watt[128 + j];
        sEteW[tid] = a;
    }
    if (EHEAD) {
        for (int i = tid; i < ET_ * 64; i += 256) sWec[i] = Wec[i];
        if (tid < ET_) sBec[tid] = bec[tid];
    }
    __syncthreads();

    int warp = tid >> 5, lane = tid & 31;
    int g  = lane >> 2;
    int tg = lane & 3;
    int e16 = blockIdx.x * 128 + warp * 16;

    float c[8][4];
#pragma unroll
    for (int nb = 0; nb < 8; nb++) {
        c[nb][0] = 0.f; c[nb][1] = 0.f; c[nb][2] = 0.f; c[nb][3] = 0.f;
    }

    const uint32_t* A0 = reinterpret_cast<const uint32_t*>(ein + (size_t)(e16 + g) * IN);
    const uint32_t* A1 = reinterpret_cast<const uint32_t*>(ein + (size_t)(e16 + g + 8) * IN);
    const uint2* bf = reinterpret_cast<const uint2*>(sB);

#pragma unroll
    for (int kb = 0; kb < KB; kb++) {
        uint32_t a0 = A0[kb * 8 + tg];
        uint32_t a1 = A1[kb * 8 + tg];
        uint32_t a2 = A0[kb * 8 + tg + 4];
        uint32_t a3 = A1[kb * 8 + tg + 4];
        if (RELU) { a0 = relu2(a0); a1 = relu2(a1); a2 = relu2(a2); a3 = relu2(a3); }
#pragma unroll
        for (int nb = 0; nb < 8; nb++) {
            uint2 b = bf[(kb * 8 + nb) * 32 + lane];
            mma_f16(c[nb], a0, a1, a2, a3, b.x, b.y);
        }
    }

    // ---- epilogue ----
    int er0 = e16 + g;
    int er1 = e16 + g + 8;
    int t0 = g_petype[er0];
    int t1 = g_petype[er1];

    uint32_t* o0 = reinterpret_cast<uint32_t*>(eaout + (size_t)er0 * 64);
    uint32_t* o1 = reinterpret_cast<uint32_t*>(eaout + (size_t)er1 * 64);

    float pre0 = 0.f, pre1 = 0.f, eo0 = 0.f, eo1 = 0.f;
#pragma unroll
    for (int nb = 0; nb < 8; nb++) {
        int col = nb * 8 + tg * 2;
        float x0 = lrelu(c[nb][0]), x1 = lrelu(c[nb][1]);
        float x2 = lrelu(c[nb][2]), x3 = lrelu(c[nb][3]);
        pre0 += x0 * sWe[col] + x1 * sWe[col + 1];
        pre1 += x2 * sWe[col] + x3 * sWe[col + 1];
        if (EHEAD) {
            eo0 += fmaxf(x0, 0.f) * sWec[t0 * 64 + col] + fmaxf(x1, 0.f) * sWec[t0 * 64 + col + 1];
            eo1 += fmaxf(x2, 0.f) * sWec[t1 * 64 + col] + fmaxf(x3, 0.f) * sWec[t1 * 64 + col + 1];
        }
        o0[nb * 4 + tg] = pack_h2(x0, x1);
        o1[nb * 4 + tg] = pack_h2(x2, x3);
    }
    pre0 += __shfl_xor_sync(0xFFFFFFFFu, pre0, 1);
    pre0 += __shfl_xor_sync(0xFFFFFFFFu, pre0, 2);
    pre1 += __shfl_xor_sync(0xFFFFFFFFu, pre1, 1);
    pre1 += __shfl_xor_sync(0xFFFFFFFFu, pre1, 2);
    if (EHEAD) {
        eo0 += __shfl_xor_sync(0xFFFFFFFFu, eo0, 1);
        eo0 += __shfl_xor_sync(0xFFFFFFFFu, eo0, 2);
        eo1 += __shfl_xor_sync(0xFFFFFFFFu, eo1, 1);
        eo1 += __shfl_xor_sync(0xFFFFFFFFu, eo1, 2);
    }

    if (tg == 0) {
        int s0 = g_psrc[er0], d0 = g_pdst[er0];
        int s1 = g_psrc[er1], d1 = g_pdst[er1];
        g_logit[er0] = lrelu(g_sI[d0] + g_sJ[s0] + pre0 + sEteW[t0]);
        g_logit[er1] = lrelu(g_sI[d1] + g_sJ[s1] + pre1 + sEteW[t1]);
        if (EHEAD) {
            eout[g_perm[er0]] = eo0 + sBec[t0];
            eout[g_perm[er1]] = eo1 + sBec[t1];
        }
    }
}

// ================= fused gather + finish =================
// block = 256 = 8 warps; warp w gathers node blockIdx*8+w, then block does the
// 128x64 Wlin GEMV per node from smem stage.
template <bool HEAD>
__global__ void __launch_bounds__(256)
gather_finish_kernel(const __half* __restrict__ ea, const float* __restrict__ Wlin,
                     const int* __restrict__ ntype,
                     const float* __restrict__ Wnc, const float* __restrict__ bnc,
                     float* __restrict__ dout) {
    __shared__ float sWlin[128 * 64];   // 32KB
    __shared__ float stage[8][128];
    __shared__ float ssum[8];

    int tid = threadIdx.x;
    for (int i = tid; i < 128 * 16; i += 256)
        reinterpret_cast<float4*>(sWlin)[i] = reinterpret_cast<const float4*>(Wlin)[i];

    int warp = tid >> 5, lane = tid & 31;
    int n = blockIdx.x * 8 + warp;   // N_ divisible by 8

    int beg = g_off[n];
    int end = g_off[n + 1];

    const uint2* ea2 = reinterpret_cast<const uint2*>(ea);
    const float4* h4 = reinterpret_cast<const float4*>(g_h);

    float4 acc = make_float4(0.f, 0.f, 0.f, 0.f);
    float sumex = 0.f;

    for (int i = beg; i < end; i++) {
        float ex = 0.f;
        if (lane == 0) ex = expf(g_logit[i]);
        ex = __shfl_sync(0xFFFFFFFFu, ex, 0);
        sumex += ex;
        float4 v;
        if (lane < 16) {
            uint2 u = ea2[(size_t)i * 16 + lane];
            __half2 p0 = *reinterpret_cast<__half2*>(&u.x);
            __half2 p1 = *reinterpret_cast<__half2*>(&u.y);
            float2 f0 = __half22float2(p0), f1 = __half22float2(p1);
            v = make_float4(f0.x, f0.y, f1.x, f1.y);
        } else {
            v = h4[(size_t)g_psrc[i] * 16 + (lane - 16)];
        }
        acc.x += ex * v.x; acc.y += ex * v.y;
        acc.z += ex * v.z; acc.w += ex * v.w;
    }

    // stage: k 0..63 = s2 (ex*h), k 64..127 = s1 (ex*ea)  [matches Wlin rows]
    int base = (lane < 16) ? (64 + lane * 4) : ((lane - 16) * 4);
    stage[warp][base + 0] = acc.x;
    stage[warp][base + 1] = acc.y;
    stage[warp][base + 2] = acc.z;
    stage[warp][base + 3] = acc.w;
    if (lane == 0) ssum[warp] = sumex;
    __syncthreads();

    float inv = 1.f / (ssum[warp] + 1e-16f);
    int o1 = lane, o2 = lane + 32;
    float r1 = 0.f, r2 = 0.f;
    const float* st = stage[warp];
#pragma unroll 4
    for (int k = 0; k < 128; k++) {
        float v = st[k];
        r1 += v * sWlin[k * 64 + o1];
        r2 += v * sWlin[k * 64 + o2];
    }
    r1 *= inv; r2 *= inv;

    if (!HEAD) {
        g_out[(size_t)n * 64 + o1] = r1;
        g_out[(size_t)n * 64 + o2] = r2;
    } else {
        int t = ntype[n];
        float p = fmaxf(r1, 0.f) * __ldg(Wnc + t * 64 + o1)
                + fmaxf(r2, 0.f) * __ldg(Wnc + t * 64 + o2);
#pragma unroll
        for (int d = 16; d > 0; d >>= 1) p += __shfl_xor_sync(0xFFFFFFFFu, p, d);
        if (lane == 0) dout[n] = p + bnc[t];
    }
}

// ================= launcher =================
extern "C" void kernel_launch(void* const* d_in, const int* in_sizes, int n_in,
                              void* d_out, int out_size) {
    const float* x     = (const float*)d_in[0];
    const int*   ei    = (const int*)d_in[1];
    const int*   ntype = (const int*)d_in[2];
    const int*   etype = (const int*)d_in[3];
    const float* eattr = (const float*)d_in[4];

    const float* Whl[3]  = {(const float*)d_in[5],  (const float*)d_in[11], (const float*)d_in[17]};
    const float* bhl[3]  = {(const float*)d_in[6],  (const float*)d_in[12], (const float*)d_in[18]};
    const float* Ete[3]  = {(const float*)d_in[7],  (const float*)d_in[13], (const float*)d_in[19]};
    const float* Wea[3]  = {(const float*)d_in[8],  (const float*)d_in[14], (const float*)d_in[20]};
    const float* Watt[3] = {(const float*)d_in[9],  (const float*)d_in[15], (const float*)d_in[21]};
    const float* Wlin[3] = {(const float*)d_in[10], (const float*)d_in[16], (const float*)d_in[22]};
    const float* Wnc = (const float*)d_in[23];
    const float* bnc = (const float*)d_in[24];
    const float* Wec = (const float*)d_in[25];
    const float* bec = (const float*)d_in[26];

    __half *e0, *e1, *ea3, *pattr;
    float *outBuf;
    cudaGetSymbolAddress((void**)&e0, g_e0);
    cudaGetSymbolAddress((void**)&e1, g_e1);
    cudaGetSymbolAddress((void**)&ea3, g_ea3);
    cudaGetSymbolAddress((void**)&pattr, g_pattr);
    cudaGetSymbolAddress((void**)&outBuf, g_out);

    const int nodeBlocks = (N_ + 127) / 128;
    const int mmaBlocks  = E_ / 128;              // 6250
    const int edgeBlocks = (E_ + 255) / 256;
    const int gfBlocks   = N_ / 8;                // 6250

    float* doutN = (float*)d_out;
    float* doutE = (float*)d_out + N_;

    // ---- CSR build + permutation ----
    zero_deg_kernel<<<(N_ + 255) / 256, 256>>>();
    hist_kernel<<<edgeBlocks, 256>>>(ei);
    scan_kernel<<<1, 1024>>>();
    scatter_perm_kernel<<<edgeBlocks, 256>>>(ei);
    perm_meta_kernel<<<edgeBlocks, 256>>>(ei, etype);
    perm_attr_kernel<<<(E_ * 4 + 255) / 256, 256>>>(eattr);

    // ---- layer 1 ----
    node_kernel<false><<<nodeBlocks, 128>>>(x, ntype, Whl[0], bhl[0], Watt[0]);
    edge_mma_kernel<FE_, false, false><<<mmaBlocks, 256>>>(
        pattr, Wea[0], Watt[0], Ete[0], e0, nullptr, nullptr, nullptr);
    gather_finish_kernel<false><<<gfBlocks, 256>>>(e0, Wlin[0], nullptr, nullptr, nullptr, nullptr);

    // ---- layer 2 ----
    node_kernel<true><<<nodeBlocks, 128>>>(outBuf, ntype, Whl[1], bhl[1], Watt[1]);
    edge_mma_kernel<H_, true, false><<<mmaBlocks, 256>>>(
        e0, Wea[1], Watt[1], Ete[1], e1, nullptr, nullptr, nullptr);
    gather_finish_kernel<false><<<gfBlocks, 256>>>(e1, Wlin[1], nullptr, nullptr, nullptr, nullptr);

    // ---- layer 3 ----
    node_kernel<true><<<nodeBlocks, 128>>>(outBuf, ntype, Whl[2], bhl[2], Watt[2]);
    edge_mma_kernel<H_, true, true><<<mmaBlocks, 256>>>(
        e1, Wea[2], Watt[2], Ete[2], ea3, Wec, bec, doutE);
    gather_finish_kernel<true><<<gfBlocks, 256>>>(ea3, Wlin[2], ntype, Wnc, bnc, doutN);
}

// round 8
// speedup vs baseline: 1.6456x; 1.1352x over previous
#include <cuda_runtime.h>
#include <cuda_fp16.h>
#include <math.h>
#include <stdint.h>

#define N_   50000
#define E_   800000
#define H_   64
#define FE_  32
#define NT_  3
#define ET_  4
#define NEG_ 0.2f

// ---------------- device scratch ----------------
__device__ __align__(16) __half g_e0[E_ * H_];     // ea layer1 (CSR order, fp16)
__device__ __align__(16) __half g_e1[E_ * H_];     // ea layer2
__device__ __align__(16) __half g_ea3[E_ * H_];    // ea layer3
__device__ __align__(16) __half g_pattr[E_ * FE_]; // permuted edge_attr (fp16)
__device__ __align__(16) __half g_h[N_ * H_];      // h (fp16, for gather)
__device__ __align__(16) float g_out[N_ * H_];
__device__ float g_sI[N_];
__device__ float g_sJ[N_];
__device__ float g_logit[E_];                      // CSR order
// CSR  (g_deg starts zero: static init; re-zeroed at end of every run)
__device__ int g_deg[N_];
__device__ int g_off[N_ + 1];
__device__ int g_cur[N_];
__device__ int g_perm[E_];
__device__ int g_psrc[E_];
__device__ int g_pdst[E_];
__device__ int g_petype[E_];

// ---------------- helpers ----------------
__device__ __forceinline__ float lrelu(float x) { return x > 0.f ? x : NEG_ * x; }

__device__ __forceinline__ void mma_f16(float (&c)[4],
                                        uint32_t a0, uint32_t a1, uint32_t a2, uint32_t a3,
                                        uint32_t b0, uint32_t b1) {
    asm volatile(
        "mma.sync.aligned.m16n8k16.row.col.f32.f16.f16.f32 "
        "{%0,%1,%2,%3}, {%4,%5,%6,%7}, {%8,%9}, {%0,%1,%2,%3};"
        : "+f"(c[0]), "+f"(c[1]), "+f"(c[2]), "+f"(c[3])
        : "r"(a0), "r"(a1), "r"(a2), "r"(a3), "r"(b0), "r"(b1));
}

__device__ __forceinline__ uint32_t relu2(uint32_t u) {
    __half2 v = *reinterpret_cast<__half2*>(&u);
    __half2 z = __float2half2_rn(0.f);
    v = __hmax2(v, z);
    return *reinterpret_cast<uint32_t*>(&v);
}

__device__ __forceinline__ uint32_t pack_h2(float a, float b) {
    __half2 h = __floats2half2_rn(a, b);
    return *reinterpret_cast<uint32_t*>(&h);
}

__device__ __forceinline__ float4 unpack_h4(uint2 u) {
    __half2 p0 = *reinterpret_cast<__half2*>(&u.x);
    __half2 p1 = *reinterpret_cast<__half2*>(&u.y);
    float2 f0 = __half22float2(p0), f1 = __half22float2(p1);
    return make_float4(f0.x, f0.y, f1.x, f1.y);
}

// ---------------- node pass body (shared) ----------------
template <bool RELU, bool HALF_OUT>
__device__ __forceinline__ void node_body(
    const float* __restrict__ xin, const int* __restrict__ ntype,
    const float* __restrict__ bhl, const float* __restrict__ Watt,
    const float4* sW, int n)
{
    int t = ntype[n];
    const float4* b4 = reinterpret_cast<const float4*>(bhl) + t * 16;
    float4 acc[16];
#pragma unroll
    for (int o4 = 0; o4 < 16; o4++) acc[o4] = __ldg(b4 + o4);

    const float4* x4 = reinterpret_cast<const float4*>(xin) + n * 16;
    const float4* W4 = sW + t * 1024;
#pragma unroll 1
    for (int kc = 0; kc < 16; kc++) {
        float4 v4 = x4[kc];
        if (RELU) {
            v4.x = fmaxf(v4.x, 0.f); v4.y = fmaxf(v4.y, 0.f);
            v4.z = fmaxf(v4.z, 0.f); v4.w = fmaxf(v4.w, 0.f);
        }
        float vv[4] = {v4.x, v4.y, v4.z, v4.w};
#pragma unroll
        for (int j = 0; j < 4; j++) {
            float v = vv[j];
            const float4* wr = W4 + (kc * 4 + j) * 16;
#pragma unroll
            for (int o4 = 0; o4 < 16; o4++) {
                float4 w = wr[o4];
                acc[o4].x += v * w.x; acc[o4].y += v * w.y;
                acc[o4].z += v * w.z; acc[o4].w += v * w.w;
            }
        }
    }

    float sI = 0.f, sJ = 0.f;
#pragma unroll
    for (int o4 = 0; o4 < 16; o4++) {
        float4 a = acc[o4];
        sI += a.x * __ldg(Watt + o4 * 4)     + a.y * __ldg(Watt + o4 * 4 + 1)
            + a.z * __ldg(Watt + o4 * 4 + 2) + a.w * __ldg(Watt + o4 * 4 + 3);
        sJ += a.x * __ldg(Watt + 64 + o4 * 4)     + a.y * __ldg(Watt + 64 + o4 * 4 + 1)
            + a.z * __ldg(Watt + 64 + o4 * 4 + 2) + a.w * __ldg(Watt + 64 + o4 * 4 + 3);
    }

    uint32_t* h32 = reinterpret_cast<uint32_t*>(g_h) + (size_t)n * 32;
#pragma unroll
    for (int o4 = 0; o4 < 16; o4++) {
        h32[o4 * 2]     = pack_h2(acc[o4].x, acc[o4].y);
        h32[o4 * 2 + 1] = pack_h2(acc[o4].z, acc[o4].w);
    }
    g_sI[n] = sI;
    g_sJ[n] = sJ;
}

// ---------------- node kernels ----------------
template <bool RELU>
__global__ void __launch_bounds__(128)
node_kernel(const float* __restrict__ xin, const int* __restrict__ ntype,
            const float* __restrict__ Whl, const float* __restrict__ bhl,
            const float* __restrict__ Watt) {
    __shared__ float4 sW[NT_ * H_ * 16];
    for (int i = threadIdx.x; i < NT_ * H_ * 16; i += blockDim.x)
        sW[i] = reinterpret_cast<const float4*>(Whl)[i];
    __syncthreads();
    int n = blockIdx.x * blockDim.x + threadIdx.x;
    if (n >= N_) return;
    node_body<RELU, true>(xin, ntype, bhl, Watt, sW, n);
}

// layer-1 node pass fused with CSR histogram (independent work, block-split)
__global__ void __launch_bounds__(128)
node1_hist_kernel(const float* __restrict__ xin, const int* __restrict__ ntype,
                  const float* __restrict__ Whl, const float* __restrict__ bhl,
                  const float* __restrict__ Watt, const int* __restrict__ ei,
                  int nodeBlocks) {
    if (blockIdx.x >= nodeBlocks) {
        int e = (blockIdx.x - nodeBlocks) * 128 + threadIdx.x;
        if (e < E_) atomicAdd(&g_deg[ei[E_ + e]], 1);
        return;
    }
    __shared__ float4 sW[NT_ * H_ * 16];
    for (int i = threadIdx.x; i < NT_ * H_ * 16; i += blockDim.x)
        sW[i] = reinterpret_cast<const float4*>(Whl)[i];
    __syncthreads();
    int n = blockIdx.x * blockDim.x + threadIdx.x;
    if (n >= N_) return;
    node_body<false, true>(xin, ntype, bhl, Watt, sW, n);
}

// ---------------- scan (single block) ----------------
__global__ void scan_kernel() {
    __shared__ int warpsum[32];
    __shared__ int s_carry;
    int tid = threadIdx.x;
    int lane = tid & 31, wid = tid >> 5;
    if (tid == 0) s_carry = 0;
    __syncthreads();
    for (int base = 0; base < N_; base += 1024) {
        int i = base + tid;
        int v = (i < N_) ? g_deg[i] : 0;
        int incl = v;
#pragma unroll
        for (int d = 1; d < 32; d <<= 1) {
            int t = __shfl_up_sync(0xFFFFFFFFu, incl, d);
            if (lane >= d) incl += t;
        }
        if (lane == 31) warpsum[wid] = incl;
        __syncthreads();
        if (wid == 0) {
            int w = warpsum[lane];
#pragma unroll
            for (int d = 1; d < 32; d <<= 1) {
                int t = __shfl_up_sync(0xFFFFFFFFu, w, d);
                if (lane >= d) w += t;
            }
            warpsum[lane] = w;
        }
        __syncthreads();
        int off = s_carry + (wid > 0 ? warpsum[wid - 1] : 0);
        int excl = off + incl - v;
        if (i < N_) { g_off[i] = excl; g_cur[i] = excl; }
        __syncthreads();
        if (tid == 0) s_carry += warpsum[31];
        __syncthreads();
    }
    if (tid == 0) g_off[N_] = s_carry;
}

// ---------------- scatter: perm + meta + attr(fp16) in one pass ----------------
__global__ void scatter_all_kernel(const int* __restrict__ ei, const int* __restrict__ etype,
                                   const float* __restrict__ eattr) {
    int e = blockIdx.x * blockDim.x + threadIdx.x;
    if (e >= E_) return;
    int dst = ei[E_ + e];
    int pos = atomicAdd(&g_cur[dst], 1);
    g_perm[pos]   = e;
    g_psrc[pos]   = ei[e];
    g_pdst[pos]   = dst;
    g_petype[pos] = etype[e];
    const float4* src = reinterpret_cast<const float4*>(eattr + (size_t)e * FE_);
    uint4* dp = reinterpret_cast<uint4*>(g_pattr + (size_t)pos * FE_);
#pragma unroll
    for (int t = 0; t < 4; t++) {
        float4 f0 = src[t * 2], f1 = src[t * 2 + 1];
        uint4 u;
        u.x = pack_h2(f0.x, f0.y); u.y = pack_h2(f0.z, f0.w);
        u.z = pack_h2(f1.x, f1.y); u.w = pack_h2(f1.z, f1.w);
        dp[t] = u;
    }
}

// ================= edge pass: fp16 tensor-core GEMM + epilogue =================
template <int IN, bool RELU, bool EHEAD>
__global__ void __launch_bounds__(256)
edge_mma_kernel(const __half* __restrict__ ein,
                const float* __restrict__ Wea,
                const float* __restrict__ Watt, const float* __restrict__ Ete,
                __half* __restrict__ eaout,
                const float* __restrict__ Wec, const float* __restrict__ bec,
                float* __restrict__ eout) {
    constexpr int KB = IN / 16;
    __shared__ uint32_t sB[KB * 8 * 64];
    __shared__ float sWe[64];
    __shared__ float sEteW[ET_];
    __shared__ float sWec[ET_ * 64];
    __shared__ float sBec[ET_];

    int tid = threadIdx.x;
    for (int i = tid; i < KB * 8 * 64; i += 256) {
        int kbnb = i >> 6;
        int j = i & 63;
        int l = j >> 1;
        int hf = j & 1;
        int kb = kbnb >> 3, nb = kbnb & 7;
        int tg = l & 3, gg = l >> 2;
        int k0 = kb * 16 + 2 * tg + hf * 8;
        int n = nb * 8 + gg;
        sB[i] = pack_h2(Wea[k0 * 64 + n], Wea[(k0 + 1) * 64 + n]);
    }
    if (tid < 64) sWe[tid] = Watt[132 + tid];
    if (tid < ET_) {
        float a = 0.f;
#pragma unroll
        for (int j = 0; j < 4; j++) a += lrelu(Ete[tid * 4 + j]) * Watt[128 + j];
        sEteW[tid] = a;
    }
    if (EHEAD) {
        for (int i = tid; i < ET_ * 64; i += 256) sWec[i] = Wec[i];
        if (tid < ET_) sBec[tid] = bec[tid];
    }
    __syncthreads();

    int warp = tid >> 5, lane = tid & 31;
    int g  = lane >> 2;
    int tg = lane & 3;
    int e16 = blockIdx.x * 128 + warp * 16;

    float c[8][4];
#pragma unroll
    for (int nb = 0; nb < 8; nb++) {
        c[nb][0] = 0.f; c[nb][1] = 0.f; c[nb][2] = 0.f; c[nb][3] = 0.f;
    }

    const uint32_t* A0 = reinterpret_cast<const uint32_t*>(ein + (size_t)(e16 + g) * IN);
    const uint32_t* A1 = reinterpret_cast<const uint32_t*>(ein + (size_t)(e16 + g + 8) * IN);
    const uint2* bf = reinterpret_cast<const uint2*>(sB);

#pragma unroll
    for (int kb = 0; kb < KB; kb++) {
        uint32_t a0 = A0[kb * 8 + tg];
        uint32_t a1 = A1[kb * 8 + tg];
        uint32_t a2 = A0[kb * 8 + tg + 4];
        uint32_t a3 = A1[kb * 8 + tg + 4];
        if (RELU) { a0 = relu2(a0); a1 = relu2(a1); a2 = relu2(a2); a3 = relu2(a3); }
#pragma unroll
        for (int nb = 0; nb < 8; nb++) {
            uint2 b = bf[(kb * 8 + nb) * 32 + lane];
            mma_f16(c[nb], a0, a1, a2, a3, b.x, b.y);
        }
    }

    // ---- epilogue ----
    int er0 = e16 + g;
    int er1 = e16 + g + 8;
    int t0 = g_petype[er0];
    int t1 = g_petype[er1];

    uint32_t* o0 = reinterpret_cast<uint32_t*>(eaout + (size_t)er0 * 64);
    uint32_t* o1 = reinterpret_cast<uint32_t*>(eaout + (size_t)er1 * 64);

    float pre0 = 0.f, pre1 = 0.f, eo0 = 0.f, eo1 = 0.f;
#pragma unroll
    for (int nb = 0; nb < 8; nb++) {
        int col = nb * 8 + tg * 2;
        float x0 = lrelu(c[nb][0]), x1 = lrelu(c[nb][1]);
        float x2 = lrelu(c[nb][2]), x3 = lrelu(c[nb][3]);
        pre0 += x0 * sWe[col] + x1 * sWe[col + 1];
        pre1 += x2 * sWe[col] + x3 * sWe[col + 1];
        if (EHEAD) {
            eo0 += fmaxf(x0, 0.f) * sWec[t0 * 64 + col] + fmaxf(x1, 0.f) * sWec[t0 * 64 + col + 1];
            eo1 += fmaxf(x2, 0.f) * sWec[t1 * 64 + col] + fmaxf(x3, 0.f) * sWec[t1 * 64 + col + 1];
        }
        o0[nb * 4 + tg] = pack_h2(x0, x1);
        o1[nb * 4 + tg] = pack_h2(x2, x3);
    }
    pre0 += __shfl_xor_sync(0xFFFFFFFFu, pre0, 1);
    pre0 += __shfl_xor_sync(0xFFFFFFFFu, pre0, 2);
    pre1 += __shfl_xor_sync(0xFFFFFFFFu, pre1, 1);
    pre1 += __shfl_xor_sync(0xFFFFFFFFu, pre1, 2);
    if (EHEAD) {
        eo0 += __shfl_xor_sync(0xFFFFFFFFu, eo0, 1);
        eo0 += __shfl_xor_sync(0xFFFFFFFFu, eo0, 2);
        eo1 += __shfl_xor_sync(0xFFFFFFFFu, eo1, 1);
        eo1 += __shfl_xor_sync(0xFFFFFFFFu, eo1, 2);
    }

    if (tg == 0) {
        int s0 = g_psrc[er0], d0 = g_pdst[er0];
        int s1 = g_psrc[er1], d1 = g_pdst[er1];
        g_logit[er0] = lrelu(g_sI[d0] + g_sJ[s0] + pre0 + sEteW[t0]);
        g_logit[er1] = lrelu(g_sI[d1] + g_sJ[s1] + pre1 + sEteW[t1]);
        if (EHEAD) {
            eout[g_perm[er0]] = eo0 + sBec[t0];
            eout[g_perm[er1]] = eo1 + sBec[t1];
        }
    }
}

// ================= fused gather + finish =================
template <bool HEAD>
__global__ void __launch_bounds__(256)
gather_finish_kernel(const __half* __restrict__ ea, const float* __restrict__ Wlin,
                     const int* __restrict__ ntype,
                     const float* __restrict__ Wnc, const float* __restrict__ bnc,
                     float* __restrict__ dout) {
    __shared__ float sWlin[128 * 64];
    __shared__ float stage[8][128];
    __shared__ float ssum[8];

    int tid = threadIdx.x;
    if (HEAD) {   // re-zero g_deg for the next graph replay (CSR already built)
        int gid = blockIdx.x * 256 + tid;
        if (gid < N_) g_deg[gid] = 0;
    }
    for (int i = tid; i < 128 * 16; i += 256)
        reinterpret_cast<float4*>(sWlin)[i] = reinterpret_cast<const float4*>(Wlin)[i];

    int warp = tid >> 5, lane = tid & 31;
    int n = blockIdx.x * 8 + warp;

    int beg = g_off[n];
    int end = g_off[n + 1];

    const uint2* ea2 = reinterpret_cast<const uint2*>(ea);
    const uint2* h2  = reinterpret_cast<const uint2*>(g_h);

    float4 acc = make_float4(0.f, 0.f, 0.f, 0.f);
    float sumex = 0.f;
    bool isEa = lane < 16;
    int sub = isEa ? lane : (lane - 16);

    int i = beg;
    for (; i + 1 < end; i += 2) {
        float ex0 = expf(g_logit[i]);
        float ex1 = expf(g_logit[i + 1]);
        uint2 u0 = isEa ? ea2[(size_t)i * 16 + sub]
                        : h2[(size_t)g_psrc[i] * 16 + sub];
        uint2 u1 = isEa ? ea2[(size_t)(i + 1) * 16 + sub]
                        : h2[(size_t)g_psrc[i + 1] * 16 + sub];
        float4 v0 = unpack_h4(u0);
        float4 v1 = unpack_h4(u1);
        sumex += ex0 + ex1;
        acc.x += ex0 * v0.x + ex1 * v1.x;
        acc.y += ex0 * v0.y + ex1 * v1.y;
        acc.z += ex0 * v0.z + ex1 * v1.z;
        acc.w += ex0 * v0.w + ex1 * v1.w;
    }
    if (i < end) {
        float ex = expf(g_logit[i]);
        uint2 u = isEa ? ea2[(size_t)i * 16 + sub]
                       : h2[(size_t)g_psrc[i] * 16 + sub];
        float4 v = unpack_h4(u);
        sumex += ex;
        acc.x += ex * v.x; acc.y += ex * v.y;
        acc.z += ex * v.z; acc.w += ex * v.w;
    }

    // stage rows: k 0..63 = ex*h (Wlin[:H]), k 64..127 = ex*ea (Wlin[H:])
    int base = isEa ? (64 + sub * 4) : (sub * 4);
    stage[warp][base + 0] = acc.x;
    stage[warp][base + 1] = acc.y;
    stage[warp][base + 2] = acc.z;
    stage[warp][base + 3] = acc.w;
    if (lane == 0) ssum[warp] = sumex;
    __syncthreads();

    float inv = 1.f / (ssum[warp] + 1e-16f);
    int o1 = lane, o2 = lane + 32;
    float r1 = 0.f, r2 = 0.f;
    const float* st = stage[warp];
#pragma unroll 4
    for (int k = 0; k < 128; k++) {
        float v = st[k];
        r1 += v * sWlin[k * 64 + o1];
        r2 += v * sWlin[k * 64 + o2];
    }
    r1 *= inv; r2 *= inv;

    if (!HEAD) {
        g_out[(size_t)n * 64 + o1] = r1;
        g_out[(size_t)n * 64 + o2] = r2;
    } else {
        int t = ntype[n];
        float p = fmaxf(r1, 0.f) * __ldg(Wnc + t * 64 + o1)
                + fmaxf(r2, 0.f) * __ldg(Wnc + t * 64 + o2);
#pragma unroll
        for (int d = 16; d > 0; d >>= 1) p += __shfl_xor_sync(0xFFFFFFFFu, p, d);
        if (lane == 0) dout[n] = p + bnc[t];
    }
}

// ================= launcher =================
extern "C" void kernel_launch(void* const* d_in, const int* in_sizes, int n_in,
                              void* d_out, int out_size) {
    const float* x     = (const float*)d_in[0];
    const int*   ei    = (const int*)d_in[1];
    const int*   ntype = (const int*)d_in[2];
    const int*   etype = (const int*)d_in[3];
    const float* eattr = (const float*)d_in[4];

    const float* Whl[3]  = {(const float*)d_in[5],  (const float*)d_in[11], (const float*)d_in[17]};
    const float* bhl[3]  = {(const float*)d_in[6],  (const float*)d_in[12], (const float*)d_in[18]};
    const float* Ete[3]  = {(const float*)d_in[7],  (const float*)d_in[13], (const float*)d_in[19]};
    const float* Wea[3]  = {(const float*)d_in[8],  (const float*)d_in[14], (const float*)d_in[20]};
    const float* Watt[3] = {(const float*)d_in[9],  (const float*)d_in[15], (const float*)d_in[21]};
    const float* Wlin[3] = {(const float*)d_in[10], (const float*)d_in[16], (const float*)d_in[22]};
    const float* Wnc = (const float*)d_in[23];
    const float* bnc = (const float*)d_in[24];
    const float* Wec = (const float*)d_in[25];
    const float* bec = (const float*)d_in[26];

    __half *e0, *e1, *ea3, *pattr;
    float *outBuf;
    cudaGetSymbolAddress((void**)&e0, g_e0);
    cudaGetSymbolAddress((void**)&e1, g_e1);
    cudaGetSymbolAddress((void**)&ea3, g_ea3);
    cudaGetSymbolAddress((void**)&pattr, g_pattr);
    cudaGetSymbolAddress((void**)&outBuf, g_out);

    const int nodeBlocks = (N_ + 127) / 128;           // 391
    const int histBlocks = (E_ + 127) / 128;           // 6250
    const int mmaBlocks  = E_ / 128;                   // 6250
    const int edgeBlocks = (E_ + 255) / 256;           // 3125
    const int gfBlocks   = N_ / 8;                     // 6250

    float* doutN = (float*)d_out;
    float* doutE = (float*)d_out + N_;

    // (1) layer-1 node transform + CSR histogram, fused
    node1_hist_kernel<<<nodeBlocks + histBlocks, 128>>>(
        x, ntype, Whl[0], bhl[0], Watt[0], ei, nodeBlocks);
    // (2) exclusive scan -> offsets
    scan_kernel<<<1, 1024>>>();
    // (3) scatter permutation + permuted meta + fp16 attr
    scatter_all_kernel<<<edgeBlocks, 256>>>(ei, etype, eattr);

    // (4) layer-1 edge GEMM   <-- ncu capture slot
    edge_mma_kernel<FE_, false, false><<<mmaBlocks, 256>>>(
        pattr, Wea[0], Watt[0], Ete[0], e0, nullptr, nullptr, nullptr);
    // (5)
    gather_finish_kernel<false><<<gfBlocks, 256>>>(e0, Wlin[0], nullptr, nullptr, nullptr, nullptr);

    // ---- layer 2 ----
    node_kernel<true><<<nodeBlocks, 128>>>(outBuf, ntype, Whl[1], bhl[1], Watt[1]);
    edge_mma_kernel<H_, true, false><<<mmaBlocks, 256>>>(
        e0, Wea[1], Watt[1], Ete[1], e1, nullptr, nullptr, nullptr);
    gather_finish_kernel<false><<<gfBlocks, 256>>>(e1, Wlin[1], nullptr, nullptr, nullptr, nullptr);

    // ---- layer 3 ----
    node_kernel<true><<<nodeBlocks, 128>>>(outBuf, ntype, Whl[2], bhl[2], Watt[2]);
    edge_mma_kernel<H_, true, true><<<mmaBlocks, 256>>>(
        e1, Wea[2], Watt[2], Ete[2], ea3, Wec, bec, doutE);
    gather_finish_kernel<true><<<gfBlocks, 256>>>(ea3, Wlin[2], ntype, Wnc, bnc, doutN);
}

// round 9
// speedup vs baseline: 1.7391x; 1.0568x over previous
#include <cuda_runtime.h>
#include <cuda_fp16.h>
#include <math.h>
#include <stdint.h>

#define N_   50000
#define E_   800000
#define H_   64
#define FE_  32
#define NT_  3
#define ET_  4
#define NEG_ 0.2f

// ---------------- device scratch ----------------
__device__ __align__(16) __half g_e0[E_ * H_];     // ea layer1 (CSR order, fp16)
__device__ __align__(16) __half g_e1[E_ * H_];     // ea layer2
__device__ __align__(16) __half g_ea3[E_ * H_];    // ea layer3
__device__ __align__(16) __half g_pattr[E_ * FE_]; // permuted edge_attr (fp16)
__device__ __align__(16) __half g_h[N_ * H_];      // h (fp16, for gather)
__device__ __align__(16) float g_out[N_ * H_];
__device__ float g_sI[N_];
__device__ float g_sJ[N_];
__device__ float g_exl[E_];                        // exp(logit), CSR order
// CSR  (g_deg starts zero: static init; re-zeroed at end of every run)
__device__ int g_deg[N_];
__device__ int g_off[N_ + 1];
__device__ int g_cur[N_];
__device__ int g_perm[E_];
__device__ int g_psrc[E_];
__device__ int g_pdst[E_];
__device__ int g_petype[E_];

// ---------------- helpers ----------------
__device__ __forceinline__ float lrelu(float x) { return x > 0.f ? x : NEG_ * x; }

__device__ __forceinline__ void mma_f16(float (&c)[4],
                                        uint32_t a0, uint32_t a1, uint32_t a2, uint32_t a3,
                                        uint32_t b0, uint32_t b1) {
    asm volatile(
        "mma.sync.aligned.m16n8k16.row.col.f32.f16.f16.f32 "
        "{%0,%1,%2,%3}, {%4,%5,%6,%7}, {%8,%9}, {%0,%1,%2,%3};"
        : "+f"(c[0]), "+f"(c[1]), "+f"(c[2]), "+f"(c[3])
        : "r"(a0), "r"(a1), "r"(a2), "r"(a3), "r"(b0), "r"(b1));
}

__device__ __forceinline__ uint32_t relu2(uint32_t u) {
    __half2 v = *reinterpret_cast<__half2*>(&u);
    __half2 z = __float2half2_rn(0.f);
    v = __hmax2(v, z);
    return *reinterpret_cast<uint32_t*>(&v);
}

__device__ __forceinline__ uint32_t pack_h2(float a, float b) {
    __half2 h = __floats2half2_rn(a, b);
    return *reinterpret_cast<uint32_t*>(&h);
}

__device__ __forceinline__ float4 unpack_h4(uint2 u) {
    __half2 p0 = *reinterpret_cast<__half2*>(&u.x);
    __half2 p1 = *reinterpret_cast<__half2*>(&u.y);
    float2 f0 = __half22float2(p0), f1 = __half22float2(p1);
    return make_float4(f0.x, f0.y, f1.x, f1.y);
}

// ---------------- node pass body (shared) ----------------
template <bool RELU>
__device__ __forceinline__ void node_body(
    const float* __restrict__ xin, const int* __restrict__ ntype,
    const float* __restrict__ bhl, const float* __restrict__ Watt,
    const float4* sW, int n)
{
    int t = ntype[n];
    const float4* b4 = reinterpret_cast<const float4*>(bhl) + t * 16;
    float4 acc[16];
#pragma unroll
    for (int o4 = 0; o4 < 16; o4++) acc[o4] = __ldg(b4 + o4);

    const float4* x4 = reinterpret_cast<const float4*>(xin) + n * 16;
    const float4* W4 = sW + t * 1024;
#pragma unroll 1
    for (int kc = 0; kc < 16; kc++) {
        float4 v4 = x4[kc];
        if (RELU) {
            v4.x = fmaxf(v4.x, 0.f); v4.y = fmaxf(v4.y, 0.f);
            v4.z = fmaxf(v4.z, 0.f); v4.w = fmaxf(v4.w, 0.f);
        }
        float vv[4] = {v4.x, v4.y, v4.z, v4.w};
#pragma unroll
        for (int j = 0; j < 4; j++) {
            float v = vv[j];
            const float4* wr = W4 + (kc * 4 + j) * 16;
#pragma unroll
            for (int o4 = 0; o4 < 16; o4++) {
                float4 w = wr[o4];
                acc[o4].x += v * w.x; acc[o4].y += v * w.y;
                acc[o4].z += v * w.z; acc[o4].w += v * w.w;
            }
        }
    }

    float sI = 0.f, sJ = 0.f;
#pragma unroll
    for (int o4 = 0; o4 < 16; o4++) {
        float4 a = acc[o4];
        sI += a.x * __ldg(Watt + o4 * 4)     + a.y * __ldg(Watt + o4 * 4 + 1)
            + a.z * __ldg(Watt + o4 * 4 + 2) + a.w * __ldg(Watt + o4 * 4 + 3);
        sJ += a.x * __ldg(Watt + 64 + o4 * 4)     + a.y * __ldg(Watt + 64 + o4 * 4 + 1)
            + a.z * __ldg(Watt + 64 + o4 * 4 + 2) + a.w * __ldg(Watt + 64 + o4 * 4 + 3);
    }

    uint32_t* h32 = reinterpret_cast<uint32_t*>(g_h) + (size_t)n * 32;
#pragma unroll
    for (int o4 = 0; o4 < 16; o4++) {
        h32[o4 * 2]     = pack_h2(acc[o4].x, acc[o4].y);
        h32[o4 * 2 + 1] = pack_h2(acc[o4].z, acc[o4].w);
    }
    g_sI[n] = sI;
    g_sJ[n] = sJ;
}

// ---------------- node kernels ----------------
template <bool RELU>
__global__ void __launch_bounds__(128)
node_kernel(const float* __restrict__ xin, const int* __restrict__ ntype,
            const float* __restrict__ Whl, const float* __restrict__ bhl,
            const float* __restrict__ Watt) {
    __shared__ float4 sW[NT_ * H_ * 16];
    for (int i = threadIdx.x; i < NT_ * H_ * 16; i += blockDim.x)
        sW[i] = reinterpret_cast<const float4*>(Whl)[i];
    __syncthreads();
    int n = blockIdx.x * blockDim.x + threadIdx.x;
    if (n >= N_) return;
    node_body<RELU>(xin, ntype, bhl, Watt, sW, n);
}

// layer-1 node pass fused with CSR histogram (independent work, block-split)
__global__ void __launch_bounds__(128)
node1_hist_kernel(const float* __restrict__ xin, const int* __restrict__ ntype,
                  const float* __restrict__ Whl, const float* __restrict__ bhl,
                  const float* __restrict__ Watt, const int* __restrict__ ei,
                  int nodeBlocks) {
    if (blockIdx.x >= nodeBlocks) {
        int e = (blockIdx.x - nodeBlocks) * 128 + threadIdx.x;
        if (e < E_) atomicAdd(&g_deg[ei[E_ + e]], 1);
        return;
    }
    __shared__ float4 sW[NT_ * H_ * 16];
    for (int i = threadIdx.x; i < NT_ * H_ * 16; i += blockDim.x)
        sW[i] = reinterpret_cast<const float4*>(Whl)[i];
    __syncthreads();
    int n = blockIdx.x * blockDim.x + threadIdx.x;
    if (n >= N_) return;
    node_body<false>(xin, ntype, bhl, Watt, sW, n);
}

// ---------------- scan (single block) ----------------
__global__ void scan_kernel() {
    __shared__ int warpsum[32];
    __shared__ int s_carry;
    int tid = threadIdx.x;
    int lane = tid & 31, wid = tid >> 5;
    if (tid == 0) s_carry = 0;
    __syncthreads();
    for (int base = 0; base < N_; base += 1024) {
        int i = base + tid;
        int v = (i < N_) ? g_deg[i] : 0;
        int incl = v;
#pragma unroll
        for (int d = 1; d < 32; d <<= 1) {
            int t = __shfl_up_sync(0xFFFFFFFFu, incl, d);
            if (lane >= d) incl += t;
        }
        if (lane == 31) warpsum[wid] = incl;
        __syncthreads();
        if (wid == 0) {
            int w = warpsum[lane];
#pragma unroll
            for (int d = 1; d < 32; d <<= 1) {
                int t = __shfl_up_sync(0xFFFFFFFFu, w, d);
                if (lane >= d) w += t;
            }
            warpsum[lane] = w;
        }
        __syncthreads();
        int off = s_carry + (wid > 0 ? warpsum[wid - 1] : 0);
        int excl = off + incl - v;
        if (i < N_) { g_off[i] = excl; g_cur[i] = excl; }
        __syncthreads();
        if (tid == 0) s_carry += warpsum[31];
        __syncthreads();
    }
    if (tid == 0) g_off[N_] = s_carry;
}

// ---------------- scatter: perm + meta + attr(fp16) in one pass ----------------
__global__ void scatter_all_kernel(const int* __restrict__ ei, const int* __restrict__ etype,
                                   const float* __restrict__ eattr) {
    int e = blockIdx.x * blockDim.x + threadIdx.x;
    if (e >= E_) return;
    int dst = ei[E_ + e];
    int pos = atomicAdd(&g_cur[dst], 1);
    g_perm[pos]   = e;
    g_psrc[pos]   = ei[e];
    g_pdst[pos]   = dst;
    g_petype[pos] = etype[e];
    const float4* src = reinterpret_cast<const float4*>(eattr + (size_t)e * FE_);
    uint4* dp = reinterpret_cast<uint4*>(g_pattr + (size_t)pos * FE_);
#pragma unroll
    for (int t = 0; t < 4; t++) {
        float4 f0 = src[t * 2], f1 = src[t * 2 + 1];
        uint4 u;
        u.x = pack_h2(f0.x, f0.y); u.y = pack_h2(f0.z, f0.w);
        u.z = pack_h2(f1.x, f1.y); u.w = pack_h2(f1.z, f1.w);
        dp[t] = u;
    }
}

// ================= edge pass: persistent fp16 MMA + epilogue =================
// grid-stride over tiles of 128 edges; B fragments built in smem ONCE per block.
template <int IN, bool RELU, bool EHEAD>
__global__ void __launch_bounds__(256)
edge_mma_kernel(const __half* __restrict__ ein,
                const float* __restrict__ Wea,
                const float* __restrict__ Watt, const float* __restrict__ Ete,
                __half* __restrict__ eaout,
                const float* __restrict__ Wec, const float* __restrict__ bec,
                float* __restrict__ eout) {
    constexpr int KB = IN / 16;
    constexpr int NTILES = E_ / 128;
    __shared__ uint32_t sB[KB * 8 * 64];
    __shared__ float sWe[64];
    __shared__ float sEteW[ET_];
    __shared__ float sWec[ET_ * 64];
    __shared__ float sBec[ET_];

    int tid = threadIdx.x;
    for (int i = tid; i < KB * 8 * 64; i += 256) {
        int kbnb = i >> 6;
        int j = i & 63;
        int l = j >> 1;
        int hf = j & 1;
        int kb = kbnb >> 3, nb = kbnb & 7;
        int tg = l & 3, gg = l >> 2;
        int k0 = kb * 16 + 2 * tg + hf * 8;
        int n = nb * 8 + gg;
        sB[i] = pack_h2(Wea[k0 * 64 + n], Wea[(k0 + 1) * 64 + n]);
    }
    if (tid < 64) sWe[tid] = Watt[132 + tid];
    if (tid < ET_) {
        float a = 0.f;
#pragma unroll
        for (int j = 0; j < 4; j++) a += lrelu(Ete[tid * 4 + j]) * Watt[128 + j];
        sEteW[tid] = a;
    }
    if (EHEAD) {
        for (int i = tid; i < ET_ * 64; i += 256) sWec[i] = Wec[i];
        if (tid < ET_) sBec[tid] = bec[tid];
    }
    __syncthreads();

    int warp = tid >> 5, lane = tid & 31;
    int g  = lane >> 2;
    int tg = lane & 3;
    const uint2* bf = reinterpret_cast<const uint2*>(sB);

    for (int tile = blockIdx.x; tile < NTILES; tile += gridDim.x) {
        int e16 = tile * 128 + warp * 16;

        float c[8][4];
#pragma unroll
        for (int nb = 0; nb < 8; nb++) {
            c[nb][0] = 0.f; c[nb][1] = 0.f; c[nb][2] = 0.f; c[nb][3] = 0.f;
        }

        const uint32_t* A0 = reinterpret_cast<const uint32_t*>(ein + (size_t)(e16 + g) * IN);
        const uint32_t* A1 = reinterpret_cast<const uint32_t*>(ein + (size_t)(e16 + g + 8) * IN);

#pragma unroll
        for (int kb = 0; kb < KB; kb++) {
            uint32_t a0 = A0[kb * 8 + tg];
            uint32_t a1 = A1[kb * 8 + tg];
            uint32_t a2 = A0[kb * 8 + tg + 4];
            uint32_t a3 = A1[kb * 8 + tg + 4];
            if (RELU) { a0 = relu2(a0); a1 = relu2(a1); a2 = relu2(a2); a3 = relu2(a3); }
#pragma unroll
            for (int nb = 0; nb < 8; nb++) {
                uint2 b = bf[(kb * 8 + nb) * 32 + lane];
                mma_f16(c[nb], a0, a1, a2, a3, b.x, b.y);
            }
        }

        // ---- epilogue ----
        int er0 = e16 + g;
        int er1 = e16 + g + 8;
        int t0 = g_petype[er0];
        int t1 = g_petype[er1];

        uint32_t* o0 = reinterpret_cast<uint32_t*>(eaout + (size_t)er0 * 64);
        uint32_t* o1 = reinterpret_cast<uint32_t*>(eaout + (size_t)er1 * 64);

        float pre0 = 0.f, pre1 = 0.f, eo0 = 0.f, eo1 = 0.f;
#pragma unroll
        for (int nb = 0; nb < 8; nb++) {
            int col = nb * 8 + tg * 2;
            float x0 = lrelu(c[nb][0]), x1 = lrelu(c[nb][1]);
            float x2 = lrelu(c[nb][2]), x3 = lrelu(c[nb][3]);
            pre0 += x0 * sWe[col] + x1 * sWe[col + 1];
            pre1 += x2 * sWe[col] + x3 * sWe[col + 1];
            if (EHEAD) {
                eo0 += fmaxf(x0, 0.f) * sWec[t0 * 64 + col] + fmaxf(x1, 0.f) * sWec[t0 * 64 + col + 1];
                eo1 += fmaxf(x2, 0.f) * sWec[t1 * 64 + col] + fmaxf(x3, 0.f) * sWec[t1 * 64 + col + 1];
            }
            o0[nb * 4 + tg] = pack_h2(x0, x1);
            o1[nb * 4 + tg] = pack_h2(x2, x3);
        }
        pre0 += __shfl_xor_sync(0xFFFFFFFFu, pre0, 1);
        pre0 += __shfl_xor_sync(0xFFFFFFFFu, pre0, 2);
        pre1 += __shfl_xor_sync(0xFFFFFFFFu, pre1, 1);
        pre1 += __shfl_xor_sync(0xFFFFFFFFu, pre1, 2);
        if (EHEAD) {
            eo0 += __shfl_xor_sync(0xFFFFFFFFu, eo0, 1);
            eo0 += __shfl_xor_sync(0xFFFFFFFFu, eo0, 2);
            eo1 += __shfl_xor_sync(0xFFFFFFFFu, eo1, 1);
            eo1 += __shfl_xor_sync(0xFFFFFFFFu, eo1, 2);
        }

        if (tg == 0) {
            int s0 = g_psrc[er0], d0 = g_pdst[er0];
            int s1 = g_psrc[er1], d1 = g_pdst[er1];
            g_exl[er0] = __expf(lrelu(g_sI[d0] + g_sJ[s0] + pre0 + sEteW[t0]));
            g_exl[er1] = __expf(lrelu(g_sI[d1] + g_sJ[s1] + pre1 + sEteW[t1]));
            if (EHEAD) {
                eout[g_perm[er0]] = eo0 + sBec[t0];
                eout[g_perm[er1]] = eo1 + sBec[t1];
            }
        }
    }
}

// ================= fused gather + finish (persistent) =================
template <bool HEAD>
__global__ void __launch_bounds__(256)
gather_finish_kernel(const __half* __restrict__ ea, const float* __restrict__ Wlin,
                     const int* __restrict__ ntype,
                     const float* __restrict__ Wnc, const float* __restrict__ bnc,
                     float* __restrict__ dout) {
    __shared__ float sWlin[128 * 64];
    __shared__ float stage[8][128];

    int tid = threadIdx.x;
    if (HEAD) {   // re-zero g_deg for the next graph replay
        for (int gid = blockIdx.x * 256 + tid; gid < N_; gid += gridDim.x * 256)
            g_deg[gid] = 0;
    }
    for (int i = tid; i < 128 * 16; i += 256)
        reinterpret_cast<float4*>(sWlin)[i] = reinterpret_cast<const float4*>(Wlin)[i];
    __syncthreads();

    int warp = tid >> 5, lane = tid & 31;
    bool isEa = lane < 16;
    int sub = isEa ? lane : (lane - 16);

    const uint2* ea2 = reinterpret_cast<const uint2*>(ea);
    const uint2* h2  = reinterpret_cast<const uint2*>(g_h);
    float* st = stage[warp];

    for (int grp = blockIdx.x; grp < N_ / 8; grp += gridDim.x) {
        int n = grp * 8 + warp;
        int beg = g_off[n];
        int end = g_off[n + 1];

        float4 acc = make_float4(0.f, 0.f, 0.f, 0.f);
        float sumex = 0.f;

        int i = beg;
        for (; i + 1 < end; i += 2) {
            float ex0 = g_exl[i];
            float ex1 = g_exl[i + 1];
            uint2 u0 = isEa ? ea2[(size_t)i * 16 + sub]
                            : h2[(size_t)g_psrc[i] * 16 + sub];
            uint2 u1 = isEa ? ea2[(size_t)(i + 1) * 16 + sub]
                            : h2[(size_t)g_psrc[i + 1] * 16 + sub];
            float4 v0 = unpack_h4(u0);
            float4 v1 = unpack_h4(u1);
            sumex += ex0 + ex1;
            acc.x += ex0 * v0.x + ex1 * v1.x;
            acc.y += ex0 * v0.y + ex1 * v1.y;
            acc.z += ex0 * v0.z + ex1 * v1.z;
            acc.w += ex0 * v0.w + ex1 * v1.w;
        }
        if (i < end) {
            float ex = g_exl[i];
            uint2 u = isEa ? ea2[(size_t)i * 16 + sub]
                           : h2[(size_t)g_psrc[i] * 16 + sub];
            float4 v = unpack_h4(u);
            sumex += ex;
            acc.x += ex * v.x; acc.y += ex * v.y;
            acc.z += ex * v.z; acc.w += ex * v.w;
        }

        // stage rows: k 0..63 = ex*h (Wlin[:H]), k 64..127 = ex*ea (Wlin[H:])
        int base = isEa ? (64 + sub * 4) : (sub * 4);
        st[base + 0] = acc.x;
        st[base + 1] = acc.y;
        st[base + 2] = acc.z;
        st[base + 3] = acc.w;
        // warp-private smem: no __syncthreads needed
        __syncwarp();

        sumex += __shfl_xor_sync(0xFFFFFFFFu, sumex, 16);  // combine halves? no-op safe
        // NOTE: each half-warp accumulated sumex over the same edge list, so lanes
        // 0..15 and 16..31 each hold the full sum already; the xor above doubles it.
        // Correct by halving:
        sumex *= 0.5f;
        float inv = 1.f / (sumex + 1e-16f);

        int o1 = lane, o2 = lane + 32;
        float r1 = 0.f, r2 = 0.f;
#pragma unroll 4
        for (int k = 0; k < 128; k++) {
            float v = st[k];
            r1 += v * sWlin[k * 64 + o1];
            r2 += v * sWlin[k * 64 + o2];
        }
        r1 *= inv; r2 *= inv;

        if (!HEAD) {
            g_out[(size_t)n * 64 + o1] = r1;
            g_out[(size_t)n * 64 + o2] = r2;
        } else {
            int t = ntype[n];
            float p = fmaxf(r1, 0.f) * __ldg(Wnc + t * 64 + o1)
                    + fmaxf(r2, 0.f) * __ldg(Wnc + t * 64 + o2);
#pragma unroll
            for (int d = 16; d > 0; d >>= 1) p += __shfl_xor_sync(0xFFFFFFFFu, p, d);
            if (lane == 0) dout[n] = p + bnc[t];
        }
        __syncwarp();
    }
}

// ================= launcher =================
extern "C" void kernel_launch(void* const* d_in, const int* in_sizes, int n_in,
                              void* d_out, int out_size) {
    const float* x     = (const float*)d_in[0];
    const int*   ei    = (const int*)d_in[1];
    const int*   ntype = (const int*)d_in[2];
    const int*   etype = (const int*)d_in[3];
    const float* eattr = (const float*)d_in[4];

    const float* Whl[3]  = {(const float*)d_in[5],  (const float*)d_in[11], (const float*)d_in[17]};
    const float* bhl[3]  = {(const float*)d_in[6],  (const float*)d_in[12], (const float*)d_in[18]};
    const float* Ete[3]  = {(const float*)d_in[7],  (const float*)d_in[13], (const float*)d_in[19]};
    const float* Wea[3]  = {(const float*)d_in[8],  (const float*)d_in[14], (const float*)d_in[20]};
    const float* Watt[3] = {(const float*)d_in[9],  (const float*)d_in[15], (const float*)d_in[21]};
    const float* Wlin[3] = {(const float*)d_in[10], (const float*)d_in[16], (const float*)d_in[22]};
    const float* Wnc = (const float*)d_in[23];
    const float* bnc = (const float*)d_in[24];
    const float* Wec = (const float*)d_in[25];
    const float* bec = (const float*)d_in[26];

    __half *e0, *e1, *ea3, *pattr;
    float *outBuf;
    cudaGetSymbolAddress((void**)&e0, g_e0);
    cudaGetSymbolAddress((void**)&e1, g_e1);
    cudaGetSymbolAddress((void**)&ea3, g_ea3);
    cudaGetSymbolAddress((void**)&pattr, g_pattr);
    cudaGetSymbolAddress((void**)&outBuf, g_out);

    const int nodeBlocks = (N_ + 127) / 128;           // 391
    const int histBlocks = (E_ + 127) / 128;           // 6250
    const int edgeBlocks = (E_ + 255) / 256;           // 3125
    const int mmaGrid    = 740;                        // persistent (5/SM)
    const int gfGrid     = 888;                        // persistent (6/SM)

    float* doutN = (float*)d_out;
    float* doutE = (float*)d_out + N_;

    // (1) layer-1 node transform + CSR histogram, fused
    node1_hist_kernel<<<nodeBlocks + histBlocks, 128>>>(
        x, ntype, Whl[0], bhl[0], Watt[0], ei, nodeBlocks);
    // (2) exclusive scan
    scan_kernel<<<1, 1024>>>();
    // (3) scatter permutation + permuted meta + fp16 attr
    scatter_all_kernel<<<edgeBlocks, 256>>>(ei, etype, eattr);

    // (4) layer-1 edge GEMM   <-- ncu capture slot
    edge_mma_kernel<FE_, false, false><<<mmaGrid, 256>>>(
        pattr, Wea[0], Watt[0], Ete[0], e0, nullptr, nullptr, nullptr);
    gather_finish_kernel<false><<<gfGrid, 256>>>(e0, Wlin[0], nullptr, nullptr, nullptr, nullptr);

    // ---- layer 2 ----
    node_kernel<true><<<nodeBlocks, 128>>>(outBuf, ntype, Whl[1], bhl[1], Watt[1]);
    edge_mma_kernel<H_, true, false><<<mmaGrid, 256>>>(
        e0, Wea[1], Watt[1], Ete[1], e1, nullptr, nullptr, nullptr);
    gather_finish_kernel<false><<<gfGrid, 256>>>(e1, Wlin[1], nullptr, nullptr, nullptr, nullptr);

    // ---- layer 3 ----
    node_kernel<true><<<nodeBlocks, 128>>>(outBuf, ntype, Whl[2], bhl[2], Watt[2]);
    edge_mma_kernel<H_, true, true><<<mmaGrid, 256>>>(
        e1, Wea[2], Watt[2], Ete[2], ea3, Wec, bec, doutE);
    gather_finish_kernel<true><<<gfGrid, 256>>>(ea3, Wlin[2], ntype, Wnc, bnc, doutN);
}

// round 10
// speedup vs baseline: 1.7926x; 1.0308x over previous
#include <cuda_runtime.h>
#include <cuda_fp16.h>
#include <math.h>
#include <stdint.h>

#define N_   50000
#define E_   800000
#define H_   64
#define FE_  32
#define NT_  3
#define ET_  4
#define NEG_ 0.2f

// ---------------- device scratch ----------------
__device__ __align__(16) __half g_e0[E_ * H_];     // ea layer1 (CSR order, fp16)
__device__ __align__(16) __half g_e1[E_ * H_];     // ea layer2
__device__ __align__(16) __half g_ea3[E_ * H_];    // ea layer3
__device__ __align__(16) __half g_pattr[E_ * FE_]; // permuted edge_attr (fp16)
__device__ __align__(16) __half g_h[N_ * H_];      // h (fp16, for gather)
__device__ __align__(16) float g_out[N_ * H_];
__device__ float g_sI[N_];
__device__ float g_sJ[N_];
__device__ float g_exl[E_];                        // exp(logit), CSR order
// CSR  (g_deg starts zero: static init; re-zeroed at end of every run)
__device__ int g_deg[N_];
__device__ int g_off[N_ + 1];
__device__ int g_cur[N_];
__device__ int g_perm[E_];
__device__ int g_psrc[E_];
__device__ int g_pdst[E_];
__device__ int g_petype[E_];

// ---------------- helpers ----------------
__device__ __forceinline__ float lrelu(float x) { return x > 0.f ? x : NEG_ * x; }

__device__ __forceinline__ void mma_f16(float (&c)[4],
                                        uint32_t a0, uint32_t a1, uint32_t a2, uint32_t a3,
                                        uint32_t b0, uint32_t b1) {
    asm volatile(
        "mma.sync.aligned.m16n8k16.row.col.f32.f16.f16.f32 "
        "{%0,%1,%2,%3}, {%4,%5,%6,%7}, {%8,%9}, {%0,%1,%2,%3};"
        : "+f"(c[0]), "+f"(c[1]), "+f"(c[2]), "+f"(c[3])
        : "r"(a0), "r"(a1), "r"(a2), "r"(a3), "r"(b0), "r"(b1));
}

__device__ __forceinline__ uint32_t relu2(uint32_t u) {
    __half2 v = *reinterpret_cast<__half2*>(&u);
    __half2 z = __float2half2_rn(0.f);
    v = __hmax2(v, z);
    return *reinterpret_cast<uint32_t*>(&v);
}

__device__ __forceinline__ uint32_t pack_h2(float a, float b) {
    __half2 h = __floats2half2_rn(a, b);
    return *reinterpret_cast<uint32_t*>(&h);
}

__device__ __forceinline__ float4 unpack_h4(uint2 u) {
    __half2 p0 = *reinterpret_cast<__half2*>(&u.x);
    __half2 p1 = *reinterpret_cast<__half2*>(&u.y);
    float2 f0 = __half22float2(p0), f1 = __half22float2(p1);
    return make_float4(f0.x, f0.y, f1.x, f1.y);
}

// ---------------- node pass body (shared) ----------------
template <bool RELU>
__device__ __forceinline__ void node_body(
    const float* __restrict__ xin, const int* __restrict__ ntype,
    const float* __restrict__ bhl, const float* __restrict__ Watt,
    const float4* sW, int n)
{
    int t = ntype[n];
    const float4* b4 = reinterpret_cast<const float4*>(bhl) + t * 16;
    float4 acc[16];
#pragma unroll
    for (int o4 = 0; o4 < 16; o4++) acc[o4] = __ldg(b4 + o4);

    const float4* x4 = reinterpret_cast<const float4*>(xin) + n * 16;
    const float4* W4 = sW + t * 1024;
#pragma unroll 1
    for (int kc = 0; kc < 16; kc++) {
        float4 v4 = x4[kc];
        if (RELU) {
            v4.x = fmaxf(v4.x, 0.f); v4.y = fmaxf(v4.y, 0.f);
            v4.z = fmaxf(v4.z, 0.f); v4.w = fmaxf(v4.w, 0.f);
        }
        float vv[4] = {v4.x, v4.y, v4.z, v4.w};
#pragma unroll
        for (int j = 0; j < 4; j++) {
            float v = vv[j];
            const float4* wr = W4 + (kc * 4 + j) * 16;
#pragma unroll
            for (int o4 = 0; o4 < 16; o4++) {
                float4 w = wr[o4];
                acc[o4].x += v * w.x; acc[o4].y += v * w.y;
                acc[o4].z += v * w.z; acc[o4].w += v * w.w;
            }
        }
    }

    float sI = 0.f, sJ = 0.f;
#pragma unroll
    for (int o4 = 0; o4 < 16; o4++) {
        float4 a = acc[o4];
        sI += a.x * __ldg(Watt + o4 * 4)     + a.y * __ldg(Watt + o4 * 4 + 1)
            + a.z * __ldg(Watt + o4 * 4 + 2) + a.w * __ldg(Watt + o4 * 4 + 3);
        sJ += a.x * __ldg(Watt + 64 + o4 * 4)     + a.y * __ldg(Watt + 64 + o4 * 4 + 1)
            + a.z * __ldg(Watt + 64 + o4 * 4 + 2) + a.w * __ldg(Watt + 64 + o4 * 4 + 3);
    }

    uint32_t* h32 = reinterpret_cast<uint32_t*>(g_h) + (size_t)n * 32;
#pragma unroll
    for (int o4 = 0; o4 < 16; o4++) {
        h32[o4 * 2]     = pack_h2(acc[o4].x, acc[o4].y);
        h32[o4 * 2 + 1] = pack_h2(acc[o4].z, acc[o4].w);
    }
    g_sI[n] = sI;
    g_sJ[n] = sJ;
}

// ---------------- node kernels ----------------
template <bool RELU>
__global__ void __launch_bounds__(128)
node_kernel(const float* __restrict__ xin, const int* __restrict__ ntype,
            const float* __restrict__ Whl, const float* __restrict__ bhl,
            const float* __restrict__ Watt) {
    __shared__ float4 sW[NT_ * H_ * 16];
    for (int i = threadIdx.x; i < NT_ * H_ * 16; i += blockDim.x)
        sW[i] = reinterpret_cast<const float4*>(Whl)[i];
    __syncthreads();
    int n = blockIdx.x * blockDim.x + threadIdx.x;
    if (n >= N_) return;
    node_body<RELU>(xin, ntype, bhl, Watt, sW, n);
}

// layer-1 node pass fused with CSR histogram (independent work, block-split)
__global__ void __launch_bounds__(128)
node1_hist_kernel(const float* __restrict__ xin, const int* __restrict__ ntype,
                  const float* __restrict__ Whl, const float* __restrict__ bhl,
                  const float* __restrict__ Watt, const int* __restrict__ ei,
                  int nodeBlocks) {
    if (blockIdx.x >= nodeBlocks) {
        int e = (blockIdx.x - nodeBlocks) * 128 + threadIdx.x;
        if (e < E_) atomicAdd(&g_deg[ei[E_ + e]], 1);
        return;
    }
    __shared__ float4 sW[NT_ * H_ * 16];
    for (int i = threadIdx.x; i < NT_ * H_ * 16; i += blockDim.x)
        sW[i] = reinterpret_cast<const float4*>(Whl)[i];
    __syncthreads();
    int n = blockIdx.x * blockDim.x + threadIdx.x;
    if (n >= N_) return;
    node_body<false>(xin, ntype, bhl, Watt, sW, n);
}

// ---------------- scan (single block) ----------------
__global__ void scan_kernel() {
    __shared__ int warpsum[32];
    __shared__ int s_carry;
    int tid = threadIdx.x;
    int lane = tid & 31, wid = tid >> 5;
    if (tid == 0) s_carry = 0;
    __syncthreads();
    for (int base = 0; base < N_; base += 1024) {
        int i = base + tid;
        int v = (i < N_) ? g_deg[i] : 0;
        int incl = v;
#pragma unroll
        for (int d = 1; d < 32; d <<= 1) {
            int t = __shfl_up_sync(0xFFFFFFFFu, incl, d);
            if (lane >= d) incl += t;
        }
        if (lane == 31) warpsum[wid] = incl;
        __syncthreads();
        if (wid == 0) {
            int w = warpsum[lane];
#pragma unroll
            for (int d = 1; d < 32; d <<= 1) {
                int t = __shfl_up_sync(0xFFFFFFFFu, w, d);
                if (lane >= d) w += t;
            }
            warpsum[lane] = w;
        }
        __syncthreads();
        int off = s_carry + (wid > 0 ? warpsum[wid - 1] : 0);
        int excl = off + incl - v;
        if (i < N_) { g_off[i] = excl; g_cur[i] = excl; }
        __syncthreads();
        if (tid == 0) s_carry += warpsum[31];
        __syncthreads();
    }
    if (tid == 0) g_off[N_] = s_carry;
}

// ---------------- scatter: perm + meta + attr(fp16) in one pass ----------------
__global__ void scatter_all_kernel(const int* __restrict__ ei, const int* __restrict__ etype,
                                   const float* __restrict__ eattr) {
    int e = blockIdx.x * blockDim.x + threadIdx.x;
    if (e >= E_) return;
    int dst = ei[E_ + e];
    int pos = atomicAdd(&g_cur[dst], 1);
    g_perm[pos]   = e;
    g_psrc[pos]   = ei[e];
    g_pdst[pos]   = dst;
    g_petype[pos] = etype[e];
    const float4* src = reinterpret_cast<const float4*>(eattr + (size_t)e * FE_);
    uint4* dp = reinterpret_cast<uint4*>(g_pattr + (size_t)pos * FE_);
#pragma unroll
    for (int t = 0; t < 4; t++) {
        float4 f0 = src[t * 2], f1 = src[t * 2 + 1];
        uint4 u;
        u.x = pack_h2(f0.x, f0.y); u.y = pack_h2(f0.z, f0.w);
        u.z = pack_h2(f1.x, f1.y); u.w = pack_h2(f1.z, f1.w);
        dp[t] = u;
    }
}

// ================= edge pass: persistent fp16 MMA + epilogue =================
// grid-stride over tiles of 128 edges; B fragments in smem ONCE per block.
// Meta + sI/sJ loads for the tile are issued BEFORE the MMA loop so their
// latency overlaps the GEMM work.
template <int IN, bool RELU, bool EHEAD>
__global__ void __launch_bounds__(256)
edge_mma_kernel(const __half* __restrict__ ein,
                const float* __restrict__ Wea,
                const float* __restrict__ Watt, const float* __restrict__ Ete,
                __half* __restrict__ eaout,
                const float* __restrict__ Wec, const float* __restrict__ bec,
                float* __restrict__ eout) {
    constexpr int KB = IN / 16;
    constexpr int NTILES = E_ / 128;
    __shared__ uint32_t sB[KB * 8 * 64];
    __shared__ float sWe[64];
    __shared__ float sEteW[ET_];
    __shared__ float sWec[ET_ * 64];
    __shared__ float sBec[ET_];

    int tid = threadIdx.x;
    for (int i = tid; i < KB * 8 * 64; i += 256) {
        int kbnb = i >> 6;
        int j = i & 63;
        int l = j >> 1;
        int hf = j & 1;
        int kb = kbnb >> 3, nb = kbnb & 7;
        int tg = l & 3, gg = l >> 2;
        int k0 = kb * 16 + 2 * tg + hf * 8;
        int n = nb * 8 + gg;
        sB[i] = pack_h2(Wea[k0 * 64 + n], Wea[(k0 + 1) * 64 + n]);
    }
    if (tid < 64) sWe[tid] = Watt[132 + tid];
    if (tid < ET_) {
        float a = 0.f;
#pragma unroll
        for (int j = 0; j < 4; j++) a += lrelu(Ete[tid * 4 + j]) * Watt[128 + j];
        sEteW[tid] = a;
    }
    if (EHEAD) {
        for (int i = tid; i < ET_ * 64; i += 256) sWec[i] = Wec[i];
        if (tid < ET_) sBec[tid] = bec[tid];
    }
    __syncthreads();

    int warp = tid >> 5, lane = tid & 31;
    int g  = lane >> 2;
    int tg = lane & 3;
    const uint2* bf = reinterpret_cast<const uint2*>(sB);

    for (int tile = blockIdx.x; tile < NTILES; tile += gridDim.x) {
        int e16 = tile * 128 + warp * 16;
        int er0 = e16 + g;
        int er1 = e16 + g + 8;

        // ---- early loads: overlap latency with GEMM ----
        int t0 = g_petype[er0];
        int t1 = g_petype[er1];
        float sij0 = 0.f, sij1 = 0.f;
        int p0 = 0, p1 = 0;
        if (tg == 0) {
            int s0 = g_psrc[er0], d0 = g_pdst[er0];
            int s1 = g_psrc[er1], d1 = g_pdst[er1];
            sij0 = g_sI[d0] + g_sJ[s0];
            sij1 = g_sI[d1] + g_sJ[s1];
            if (EHEAD) { p0 = g_perm[er0]; p1 = g_perm[er1]; }
        }

        float c[8][4];
#pragma unroll
        for (int nb = 0; nb < 8; nb++) {
            c[nb][0] = 0.f; c[nb][1] = 0.f; c[nb][2] = 0.f; c[nb][3] = 0.f;
        }

        const uint32_t* A0 = reinterpret_cast<const uint32_t*>(ein + (size_t)er0 * IN);
        const uint32_t* A1 = reinterpret_cast<const uint32_t*>(ein + (size_t)er1 * IN);

#pragma unroll
        for (int kb = 0; kb < KB; kb++) {
            uint32_t a0 = A0[kb * 8 + tg];
            uint32_t a1 = A1[kb * 8 + tg];
            uint32_t a2 = A0[kb * 8 + tg + 4];
            uint32_t a3 = A1[kb * 8 + tg + 4];
            if (RELU) { a0 = relu2(a0); a1 = relu2(a1); a2 = relu2(a2); a3 = relu2(a3); }
#pragma unroll
            for (int nb = 0; nb < 8; nb++) {
                uint2 b = bf[(kb * 8 + nb) * 32 + lane];
                mma_f16(c[nb], a0, a1, a2, a3, b.x, b.y);
            }
        }

        // ---- epilogue ----
        uint32_t* o0 = reinterpret_cast<uint32_t*>(eaout + (size_t)er0 * 64);
        uint32_t* o1 = reinterpret_cast<uint32_t*>(eaout + (size_t)er1 * 64);

        float pre0 = 0.f, pre1 = 0.f, eo0 = 0.f, eo1 = 0.f;
#pragma unroll
        for (int nb = 0; nb < 8; nb++) {
            int col = nb * 8 + tg * 2;
            float x0 = lrelu(c[nb][0]), x1 = lrelu(c[nb][1]);
            float x2 = lrelu(c[nb][2]), x3 = lrelu(c[nb][3]);
            pre0 += x0 * sWe[col] + x1 * sWe[col + 1];
            pre1 += x2 * sWe[col] + x3 * sWe[col + 1];
            if (EHEAD) {
                eo0 += fmaxf(x0, 0.f) * sWec[t0 * 64 + col] + fmaxf(x1, 0.f) * sWec[t0 * 64 + col + 1];
                eo1 += fmaxf(x2, 0.f) * sWec[t1 * 64 + col] + fmaxf(x3, 0.f) * sWec[t1 * 64 + col + 1];
            }
            o0[nb * 4 + tg] = pack_h2(x0, x1);
            o1[nb * 4 + tg] = pack_h2(x2, x3);
        }
        pre0 += __shfl_xor_sync(0xFFFFFFFFu, pre0, 1);
        pre0 += __shfl_xor_sync(0xFFFFFFFFu, pre0, 2);
        pre1 += __shfl_xor_sync(0xFFFFFFFFu, pre1, 1);
        pre1 += __shfl_xor_sync(0xFFFFFFFFu, pre1, 2);
        if (EHEAD) {
            eo0 += __shfl_xor_sync(0xFFFFFFFFu, eo0, 1);
            eo0 += __shfl_xor_sync(0xFFFFFFFFu, eo0, 2);
            eo1 += __shfl_xor_sync(0xFFFFFFFFu, eo1, 1);
            eo1 += __shfl_xor_sync(0xFFFFFFFFu, eo1, 2);
        }

        if (tg == 0) {
            g_exl[er0] = __expf(lrelu(sij0 + pre0 + sEteW[t0]));
            g_exl[er1] = __expf(lrelu(sij1 + pre1 + sEteW[t1]));
            if (EHEAD) {
                eout[p0] = eo0 + sBec[t0];
                eout[p1] = eo1 + sBec[t1];
            }
        }
    }
}

// ================= fused gather + finish (persistent) =================
template <bool HEAD>
__global__ void __launch_bounds__(256)
gather_finish_kernel(const __half* __restrict__ ea, const float* __restrict__ Wlin,
                     const int* __restrict__ ntype,
                     const float* __restrict__ Wnc, const float* __restrict__ bnc,
                     float* __restrict__ dout) {
    __shared__ float sWlin[128 * 64];
    __shared__ float stage[8][128];

    int tid = threadIdx.x;
    if (HEAD) {   // re-zero g_deg for the next graph replay
        for (int gid = blockIdx.x * 256 + tid; gid < N_; gid += gridDim.x * 256)
            g_deg[gid] = 0;
    }
    for (int i = tid; i < 128 * 16; i += 256)
        reinterpret_cast<float4*>(sWlin)[i] = reinterpret_cast<const float4*>(Wlin)[i];
    __syncthreads();

    int warp = tid >> 5, lane = tid & 31;
    bool isEa = lane < 16;
    int sub = isEa ? lane : (lane - 16);

    const uint2* ea2 = reinterpret_cast<const uint2*>(ea);
    const uint2* h2  = reinterpret_cast<const uint2*>(g_h);
    float* st = stage[warp];

    for (int grp = blockIdx.x; grp < N_ / 8; grp += gridDim.x) {
        int n = grp * 8 + warp;
        int beg = g_off[n];
        int end = g_off[n + 1];

        float4 acc = make_float4(0.f, 0.f, 0.f, 0.f);
        float sumex = 0.f;

        int i = beg;
        for (; i + 3 < end; i += 4) {
            float ex0 = g_exl[i],     ex1 = g_exl[i + 1];
            float ex2 = g_exl[i + 2], ex3 = g_exl[i + 3];
            uint2 u0 = isEa ? ea2[(size_t)i * 16 + sub]       : h2[(size_t)g_psrc[i] * 16 + sub];
            uint2 u1 = isEa ? ea2[(size_t)(i + 1) * 16 + sub] : h2[(size_t)g_psrc[i + 1] * 16 + sub];
            uint2 u2 = isEa ? ea2[(size_t)(i + 2) * 16 + sub] : h2[(size_t)g_psrc[i + 2] * 16 + sub];
            uint2 u3 = isEa ? ea2[(size_t)(i + 3) * 16 + sub] : h2[(size_t)g_psrc[i + 3] * 16 + sub];
            float4 v0 = unpack_h4(u0), v1 = unpack_h4(u1);
            float4 v2 = unpack_h4(u2), v3 = unpack_h4(u3);
            sumex += (ex0 + ex1) + (ex2 + ex3);
            acc.x += ex0 * v0.x + ex1 * v1.x + ex2 * v2.x + ex3 * v3.x;
            acc.y += ex0 * v0.y + ex1 * v1.y + ex2 * v2.y + ex3 * v3.y;
            acc.z += ex0 * v0.z + ex1 * v1.z + ex2 * v2.z + ex3 * v3.z;
            acc.w += ex0 * v0.w + ex1 * v1.w + ex2 * v2.w + ex3 * v3.w;
        }
        for (; i < end; i++) {
            float ex = g_exl[i];
            uint2 u = isEa ? ea2[(size_t)i * 16 + sub]
                           : h2[(size_t)g_psrc[i] * 16 + sub];
            float4 v = unpack_h4(u);
            sumex += ex;
            acc.x += ex * v.x; acc.y += ex * v.y;
            acc.z += ex * v.z; acc.w += ex * v.w;
        }

        // stage rows: k 0..63 = ex*h (Wlin[:H]), k 64..127 = ex*ea (Wlin[H:])
        int base = isEa ? (64 + sub * 4) : (sub * 4);
        st[base + 0] = acc.x;
        st[base + 1] = acc.y;
        st[base + 2] = acc.z;
        st[base + 3] = acc.w;
        __syncwarp();

        // both half-warps computed the full sumex; xor-16 then halve keeps it exact
        sumex += __shfl_xor_sync(0xFFFFFFFFu, sumex, 16);
        sumex *= 0.5f;
        float inv = 1.f / (sumex + 1e-16f);

        int o1 = lane, o2 = lane + 32;
        float r1 = 0.f, r2 = 0.f;
#pragma unroll 4
        for (int k = 0; k < 128; k++) {
            float v = st[k];
            r1 += v * sWlin[k * 64 + o1];
            r2 += v * sWlin[k * 64 + o2];
        }
        r1 *= inv; r2 *= inv;

        if (!HEAD) {
            g_out[(size_t)n * 64 + o1] = r1;
            g_out[(size_t)n * 64 + o2] = r2;
        } else {
            int t = ntype[n];
            float p = fmaxf(r1, 0.f) * __ldg(Wnc + t * 64 + o1)
                    + fmaxf(r2, 0.f) * __ldg(Wnc + t * 64 + o2);
#pragma unroll
            for (int d = 16; d > 0; d >>= 1) p += __shfl_xor_sync(0xFFFFFFFFu, p, d);
            if (lane == 0) dout[n] = p + bnc[t];
        }
        __syncwarp();
    }
}

// ================= launcher =================
extern "C" void kernel_launch(void* const* d_in, const int* in_sizes, int n_in,
                              void* d_out, int out_size) {
    const float* x     = (const float*)d_in[0];
    const int*   ei    = (const int*)d_in[1];
    const int*   ntype = (const int*)d_in[2];
    const int*   etype = (const int*)d_in[3];
    const float* eattr = (const float*)d_in[4];

    const float* Whl[3]  = {(const float*)d_in[5],  (const float*)d_in[11], (const float*)d_in[17]};
    const float* bhl[3]  = {(const float*)d_in[6],  (const float*)d_in[12], (const float*)d_in[18]};
    const float* Ete[3]  = {(const float*)d_in[7],  (const float*)d_in[13], (const float*)d_in[19]};
    const float* Wea[3]  = {(const float*)d_in[8],  (const float*)d_in[14], (const float*)d_in[20]};
    const float* Watt[3] = {(const float*)d_in[9],  (const float*)d_in[15], (const float*)d_in[21]};
    const float* Wlin[3] = {(const float*)d_in[10], (const float*)d_in[16], (const float*)d_in[22]};
    const float* Wnc = (const float*)d_in[23];
    const float* bnc = (const float*)d_in[24];
    const float* Wec = (const float*)d_in[25];
    const float* bec = (const float*)d_in[26];

    __half *e0, *e1, *ea3, *pattr;
    float *outBuf;
    cudaGetSymbolAddress((void**)&e0, g_e0);
    cudaGetSymbolAddress((void**)&e1, g_e1);
    cudaGetSymbolAddress((void**)&ea3, g_ea3);
    cudaGetSymbolAddress((void**)&pattr, g_pattr);
    cudaGetSymbolAddress((void**)&outBuf, g_out);

    const int nodeBlocks = (N_ + 127) / 128;           // 391
    const int histBlocks = (E_ + 127) / 128;           // 6250
    const int edgeBlocks = (E_ + 255) / 256;           // 3125
    const int mmaGrid    = 592;                        // 4/SM exact residency
    const int gfGrid     = 888;                        // 6/SM exact

    float* doutN = (float*)d_out;
    float* doutE = (float*)d_out + N_;

    // (1) layer-1 node transform + CSR histogram, fused
    node1_hist_kernel<<<nodeBlocks + histBlocks, 128>>>(
        x, ntype, Whl[0], bhl[0], Watt[0], ei, nodeBlocks);
    // (2) exclusive scan
    scan_kernel<<<1, 1024>>>();
    // (3) scatter permutation + permuted meta + fp16 attr
    scatter_all_kernel<<<edgeBlocks, 256>>>(ei, etype, eattr);

    // (4) layer-1 edge GEMM   <-- ncu capture slot
    edge_mma_kernel<FE_, false, false><<<mmaGrid, 256>>>(
        pattr, Wea[0], Watt[0], Ete[0], e0, nullptr, nullptr, nullptr);
    gather_finish_kernel<false><<<gfGrid, 256>>>(e0, Wlin[0], nullptr, nullptr, nullptr, nullptr);

    // ---- layer 2 ----
    node_kernel<true><<<nodeBlocks, 128>>>(outBuf, ntype, Whl[1], bhl[1], Watt[1]);
    edge_mma_kernel<H_, true, false><<<mmaGrid, 256>>>(
        e0, Wea[1], Watt[1], Ete[1], e1, nullptr, nullptr, nullptr);
    gather_finish_kernel<false><<<gfGrid, 256>>>(e1, Wlin[1], nullptr, nullptr, nullptr, nullptr);

    // ---- layer 3 ----
    node_kernel<true><<<nodeBlocks, 128>>>(outBuf, ntype, Whl[2], bhl[2], Watt[2]);
    edge_mma_kernel<H_, true, true><<<mmaGrid, 256>>>(
        e1, Wea[2], Watt[2], Ete[2], ea3, Wec, bec, doutE);
    gather_finish_kernel<true><<<gfGrid, 256>>>(ea3, Wlin[2], ntype, Wnc, bnc, doutN);
}